// round 2
// baseline (speedup 1.0000x reference)
#include <cuda_runtime.h>
#include <math.h>

// ---------------- problem constants ----------------
#define Nn   2048
#define Dd   128
#define Hh   8
#define FFd  512
#define OUTd 64
#define Ll   3
#define HSd  8
#define DEGMAX 64

// ---------------- device scratch (no allocations allowed) ----------------
__device__ float g_h[Nn * Dd];                     // 1 MB
__device__ float g_xn[Nn * Dd];                    // 1 MB
__device__ float g_bias[(size_t)Nn * Nn];          // 16 MB
__device__ float g_q[Hh * Nn * Dd];                // 8 MB
__device__ float g_k[Hh * Nn * Dd];                // 8 MB
__device__ float g_v[Hh * Nn * Dd];                // 8 MB
__device__ float g_scores[(size_t)Hh * Nn * Nn];   // 128 MB
__device__ float g_o[Nn * Hh * Dd];                // 8 MB
__device__ float g_ff[Nn * FFd];                   // 4 MB
__device__ int   g_indeg[Nn];
__device__ int   g_outdeg[Nn];

// ---------------- degree counting ----------------
__global__ void deg_zero_kernel() {
    int i = blockIdx.x * blockDim.x + threadIdx.x;
    if (i < Nn) { g_indeg[i] = 0; g_outdeg[i] = 0; }
}

__global__ void deg_count_kernel(const int* __restrict__ ei, int E) {
    int e = blockIdx.x * blockDim.x + threadIdx.x;
    if (e < E) {
        atomicAdd(&g_outdeg[ei[e]], 1);      // src = edge_index[0][e]
        atomicAdd(&g_indeg[ei[E + e]], 1);   // dst = edge_index[1][e]
    }
}

// ---------------- input embedding + centrality ----------------
__global__ void embed_kernel(const float* __restrict__ x, const float* __restrict__ W,
                             const float* __restrict__ b, const float* __restrict__ z_in,
                             const float* __restrict__ z_out) {
    int n = blockIdx.x, d = threadIdx.x;  // 128 threads
    float acc = b[d];
#pragma unroll
    for (int i = 0; i < 16; i++) acc = fmaf(x[n * 16 + i], W[i * Dd + d], acc);
    int di = min(g_indeg[n],  DEGMAX - 1);
    int dn = min(g_outdeg[n], DEGMAX - 1);
    g_h[n * Dd + d] = acc + z_in[di * Dd + d] + z_out[dn * Dd + d];
}

// ---------------- spatial (Gaussian) bias  b[i,j] ----------------
__global__ void spbias_kernel(const float* __restrict__ pos, const float* __restrict__ mu,
                              const float* __restrict__ sigma, const float* __restrict__ w,
                              const float* __restrict__ b0) {
    long long idx = (long long)blockIdx.x * blockDim.x + threadIdx.x;
    int i = (int)(idx / Nn), j = (int)(idx % Nn);
    float dx = pos[i * 3 + 0] - pos[j * 3 + 0];
    float dy = pos[i * 3 + 1] - pos[j * 3 + 1];
    float dz = pos[i * 3 + 2] - pos[j * 3 + 2];
    float d = sqrtf(dx * dx + dy * dy + dz * dz + 1e-12f);
    float acc = b0[0];
#pragma unroll
    for (int t = 0; t < HSd; t++) {
        float u = (d - mu[t]) / sigma[t];
        acc = fmaf(__expf(-0.5f * u * u), w[t], acc);
    }
    g_bias[idx] = acc;
}

// ---------------- LayerNorm (one 128-thread block per row) ----------------
__global__ void ln_kernel(const float* __restrict__ x, float* __restrict__ y,
                          const float* __restrict__ g, const float* __restrict__ b) {
    int n = blockIdx.x, t = threadIdx.x;
    float v = x[n * Dd + t];
    float s = v, sq = v * v;
#pragma unroll
    for (int o = 16; o > 0; o >>= 1) {
        s  += __shfl_xor_sync(0xffffffffu, s,  o);
        sq += __shfl_xor_sync(0xffffffffu, sq, o);
    }
    __shared__ float ss[4], ssq[4];
    if ((t & 31) == 0) { ss[t >> 5] = s; ssq[t >> 5] = sq; }
    __syncthreads();
    float S = ss[0] + ss[1] + ss[2] + ss[3];
    float Q = ssq[0] + ssq[1] + ssq[2] + ssq[3];
    float mean = S * (1.0f / Dd);
    float var  = Q * (1.0f / Dd) - mean * mean;
    y[n * Dd + t] = (v - mean) * rsqrtf(var + 1e-5f) * g[t] + b[t];
}

// ---------------- row softmax over 2048 cols (one 256-thread block per row) ----------------
__global__ void __launch_bounds__(256) softmax_kernel(float* __restrict__ Sbase) {
    float* row = Sbase + (long long)blockIdx.x * Nn;
    int t = threadIdx.x;
    // each thread covers 8 columns, vectorized
    float4 v0 = *reinterpret_cast<const float4*>(row + t * 4);
    float4 v1 = *reinterpret_cast<const float4*>(row + 1024 + t * 4);
    float m = fmaxf(fmaxf(fmaxf(v0.x, v0.y), fmaxf(v0.z, v0.w)),
                    fmaxf(fmaxf(v1.x, v1.y), fmaxf(v1.z, v1.w)));
#pragma unroll
    for (int o = 16; o > 0; o >>= 1) m = fmaxf(m, __shfl_xor_sync(0xffffffffu, m, o));
    __shared__ float sm[8];
    if ((t & 31) == 0) sm[t >> 5] = m;
    __syncthreads();
    m = fmaxf(fmaxf(fmaxf(sm[0], sm[1]), fmaxf(sm[2], sm[3])),
              fmaxf(fmaxf(sm[4], sm[5]), fmaxf(sm[6], sm[7])));

    v0.x = __expf(v0.x - m); v0.y = __expf(v0.y - m);
    v0.z = __expf(v0.z - m); v0.w = __expf(v0.w - m);
    v1.x = __expf(v1.x - m); v1.y = __expf(v1.y - m);
    v1.z = __expf(v1.z - m); v1.w = __expf(v1.w - m);
    float s = v0.x + v0.y + v0.z + v0.w + v1.x + v1.y + v1.z + v1.w;
#pragma unroll
    for (int o = 16; o > 0; o >>= 1) s += __shfl_xor_sync(0xffffffffu, s, o);
    __shared__ float sw[8];
    if ((t & 31) == 0) sw[t >> 5] = s;
    __syncthreads();
    s = sw[0] + sw[1] + sw[2] + sw[3] + sw[4] + sw[5] + sw[6] + sw[7];
    float inv = 1.0f / s;
    v0.x *= inv; v0.y *= inv; v0.z *= inv; v0.w *= inv;
    v1.x *= inv; v1.y *= inv; v1.z *= inv; v1.w *= inv;
    *reinterpret_cast<float4*>(row + t * 4) = v0;
    *reinterpret_cast<float4*>(row + 1024 + t * 4) = v1;
}

// ---------------- generic tiled SGEMM ----------------
// C[M,Nc] = epi( A[M,K] * (TB ? B[Nc,K]^T : B[K,Nc]) )
// EPI: 0 = +bias[col]        1 = gelu(+bias[col])    2 = C += acc + bias[col] (residual)
//      3 = acc*alpha + bias2d[row*Nc+col]            4 = plain store
// Batched over blockIdx.z with element strides sA/sB/sC (and sBias for 0..2).
// Requires: M % BM == 0, Nc % BN == 0, K % 16 == 0. 256 threads.
template <int BM, int BN, int TM, int TN, bool TB, int EPI>
__global__ void __launch_bounds__(256)
gemm_kernel(const float* __restrict__ A, int lda, long long sA,
            const float* __restrict__ B, int ldb, long long sB,
            float* __restrict__ C, int ldc, long long sC,
            const float* __restrict__ bias, int sBias,
            const float* __restrict__ bias2d,
            float alpha, int M, int Nc, int K)
{
    constexpr int BK = 16;
    constexpr int TX = BN / TN;

    const int z = blockIdx.z;
    A += (long long)z * sA;
    B += (long long)z * sB;
    C += (long long)z * sC;
    if (EPI == 0 || EPI == 1 || EPI == 2) bias += (long long)z * sBias;

    __shared__ __align__(16) float As[BM][BK + 2];
    __shared__ __align__(16) float Bs[BK][BN + 4];

    const int tid = threadIdx.x;
    const int tx = tid % TX;
    const int ty = tid / TX;
    const int rowBase = blockIdx.y * BM;
    const int colBase = blockIdx.x * BN;

    float acc[TM][TN];
#pragma unroll
    for (int i = 0; i < TM; i++)
#pragma unroll
        for (int j = 0; j < TN; j++) acc[i][j] = 0.f;

    for (int k0 = 0; k0 < K; k0 += BK) {
#pragma unroll
        for (int it = 0; it < (BM * BK) / (256 * 4); it++) {
            int idx = (tid + it * 256) * 4;      // 4 consecutive k's per thread
            int kk = idx % BK;
            int r  = idx / BK;
            float4 av = *reinterpret_cast<const float4*>(
                &A[(long long)(rowBase + r) * lda + k0 + kk]);
            As[r][kk + 0] = av.x; As[r][kk + 1] = av.y;
            As[r][kk + 2] = av.z; As[r][kk + 3] = av.w;
        }
        if (TB) {
#pragma unroll
            for (int it = 0; it < (BN * BK) / (256 * 4); it++) {
                int idx = (tid + it * 256) * 4;
                int kk = idx % BK;
                int c  = idx / BK;
                float4 bv = *reinterpret_cast<const float4*>(
                    &B[(long long)(colBase + c) * ldb + k0 + kk]);
                Bs[kk + 0][c] = bv.x; Bs[kk + 1][c] = bv.y;
                Bs[kk + 2][c] = bv.z; Bs[kk + 3][c] = bv.w;
            }
        } else {
#pragma unroll
            for (int it = 0; it < (BN * BK) / (256 * 4); it++) {
                int idx = (tid + it * 256) * 4;
                int c  = idx % BN;
                int kr = idx / BN;
                float4 bv = *reinterpret_cast<const float4*>(
                    &B[(long long)(k0 + kr) * ldb + colBase + c]);
                *reinterpret_cast<float4*>(&Bs[kr][c]) = bv;
            }
        }
        __syncthreads();
#pragma unroll
        for (int kk = 0; kk < BK; kk++) {
            float a[TM], bfr[TN];
#pragma unroll
            for (int i = 0; i < TM; i++) a[i] = As[ty * TM + i][kk];
#pragma unroll
            for (int jv = 0; jv < TN / 4; jv++) {
                float4 bv = *reinterpret_cast<const float4*>(&Bs[kk][tx * TN + jv * 4]);
                bfr[jv * 4 + 0] = bv.x; bfr[jv * 4 + 1] = bv.y;
                bfr[jv * 4 + 2] = bv.z; bfr[jv * 4 + 3] = bv.w;
            }
#pragma unroll
            for (int i = 0; i < TM; i++)
#pragma unroll
                for (int j = 0; j < TN; j++)
                    acc[i][j] = fmaf(a[i], bfr[j], acc[i][j]);
        }
        __syncthreads();
    }

#pragma unroll
    for (int i = 0; i < TM; i++) {
        int row = rowBase + ty * TM + i;
#pragma unroll
        for (int j = 0; j < TN; j++) {
            int col = colBase + tx * TN + j;
            float v = acc[i][j];
            long long ci = (long long)row * ldc + col;
            if (EPI == 0) {
                C[ci] = v + bias[col];
            } else if (EPI == 1) {
                v += bias[col];
                C[ci] = 0.5f * v * (1.0f + erff(v * 0.70710678118654752f));
            } else if (EPI == 2) {
                C[ci] += v + bias[col];
            } else if (EPI == 3) {
                C[ci] = v * alpha + bias2d[(long long)row * Nc + col];
            } else {
                C[ci] = v;
            }
        }
    }
}

// ---------------- launcher ----------------
extern "C" void kernel_launch(void* const* d_in, const int* in_sizes, int n_in,
                              void* d_out, int out_size)
{
    (void)n_in; (void)out_size;
    const float* x         = (const float*)d_in[0];
    const int*   ei        = (const int*)  d_in[1];
    const float* pos       = (const float*)d_in[3];
    const float* node_in_w = (const float*)d_in[4];
    const float* node_in_b = (const float*)d_in[5];
    const float* z_in      = (const float*)d_in[8];
    const float* z_out     = (const float*)d_in[9];
    const float* sp_mu     = (const float*)d_in[10];
    const float* sp_sigma  = (const float*)d_in[11];
    const float* sp_w      = (const float*)d_in[12];
    const float* sp_b      = (const float*)d_in[13];
    const float* Wq        = (const float*)d_in[14];
    const float* bq        = (const float*)d_in[15];
    const float* Wk        = (const float*)d_in[16];
    const float* bk        = (const float*)d_in[17];
    const float* Wv        = (const float*)d_in[18];
    const float* bv        = (const float*)d_in[19];
    const float* Wo        = (const float*)d_in[20];
    const float* bo        = (const float*)d_in[21];
    const float* ln1_g     = (const float*)d_in[22];
    const float* ln1_b     = (const float*)d_in[23];
    const float* ln2_g     = (const float*)d_in[24];
    const float* ln2_b     = (const float*)d_in[25];
    const float* ff1_w     = (const float*)d_in[26];
    const float* ff1_b     = (const float*)d_in[27];
    const float* ff2_w     = (const float*)d_in[28];
    const float* ff2_b     = (const float*)d_in[29];
    const float* out_w     = (const float*)d_in[30];
    const float* out_b     = (const float*)d_in[31];
    float* out = (float*)d_out;

    const int E = in_sizes[1] / 2;
    const float scale = 0.08838834764831845f;  // 1/sqrt(128)

    float *p_h, *p_xn, *p_bias, *p_q, *p_k, *p_v, *p_s, *p_o, *p_ff;
    cudaGetSymbolAddress((void**)&p_h,    g_h);
    cudaGetSymbolAddress((void**)&p_xn,   g_xn);
    cudaGetSymbolAddress((void**)&p_bias, g_bias);
    cudaGetSymbolAddress((void**)&p_q,    g_q);
    cudaGetSymbolAddress((void**)&p_k,    g_k);
    cudaGetSymbolAddress((void**)&p_v,    g_v);
    cudaGetSymbolAddress((void**)&p_s,    g_scores);
    cudaGetSymbolAddress((void**)&p_o,    g_o);
    cudaGetSymbolAddress((void**)&p_ff,   g_ff);

    // --- preprocessing ---
    deg_zero_kernel<<<(Nn + 255) / 256, 256>>>();
    deg_count_kernel<<<(E + 255) / 256, 256>>>(ei, E);
    embed_kernel<<<Nn, Dd>>>(x, node_in_w, node_in_b, z_in, z_out);
    spbias_kernel<<<(int)(((long long)Nn * Nn) / 256), 256>>>(pos, sp_mu, sp_sigma, sp_w, sp_b);

    const long long sHead = (long long)Nn * Dd;   // per-head q/k/v stride
    const long long sW    = (long long)Dd * Dd;   // per-head weight stride
    const long long sS    = (long long)Nn * Nn;   // per-head scores stride

    for (int l = 0; l < Ll; l++) {
        // LN1
        ln_kernel<<<Nn, Dd>>>(p_h, p_xn, ln1_g + l * Dd, ln1_b + l * Dd);

        // QKV projections (batched over heads): [2048,128] @ [128,128] + bias
        dim3 gQ(Dd / 64, Nn / 64, Hh);
        gemm_kernel<64, 64, 4, 4, false, 0><<<gQ, 256>>>(
            p_xn, Dd, 0, Wq + (long long)l * Hh * sW, Dd, sW,
            p_q, Dd, sHead, bq + (long long)l * Hh * Dd, Dd, nullptr, 1.f, Nn, Dd, Dd);
        gemm_kernel<64, 64, 4, 4, false, 0><<<gQ, 256>>>(
            p_xn, Dd, 0, Wk + (long long)l * Hh * sW, Dd, sW,
            p_k, Dd, sHead, bk + (long long)l * Hh * Dd, Dd, nullptr, 1.f, Nn, Dd, Dd);
        gemm_kernel<64, 64, 4, 4, false, 0><<<gQ, 256>>>(
            p_xn, Dd, 0, Wv + (long long)l * Hh * sW, Dd, sW,
            p_v, Dd, sHead, bv + (long long)l * Hh * Dd, Dd, nullptr, 1.f, Nn, Dd, Dd);

        // scores = q @ k^T * scale + bias   [8][2048,2048]
        dim3 gS(Nn / 128, Nn / 128, Hh);
        gemm_kernel<128, 128, 8, 8, true, 3><<<gS, 256>>>(
            p_q, Dd, sHead, p_k, Dd, sHead,
            p_s, Nn, sS, nullptr, 0, p_bias, scale, Nn, Nn, Dd);

        // softmax over rows
        softmax_kernel<<<Hh * Nn, 256>>>(p_s);

        // o[n, h*D+e] = attn[h] @ v[h]
        dim3 gA(Dd / 128, Nn / 128, Hh);
        gemm_kernel<128, 128, 8, 8, false, 4><<<gA, 256>>>(
            p_s, Nn, sS, p_v, Dd, sHead,
            p_o, Hh * Dd, Dd, nullptr, 0, nullptr, 1.f, Nn, Dd, Nn);

        // h += o @ Wo + bo
        dim3 gW2(Dd / 64, Nn / 64, 1);
        gemm_kernel<64, 64, 4, 4, false, 2><<<gW2, 256>>>(
            p_o, Hh * Dd, 0, Wo + (long long)l * Hh * Dd * Dd, Dd, 0,
            p_h, Dd, 0, bo + l * Dd, 0, nullptr, 1.f, Nn, Dd, Hh * Dd);

        // LN2
        ln_kernel<<<Nn, Dd>>>(p_h, p_xn, ln2_g + l * Dd, ln2_b + l * Dd);

        // ff = gelu(xn2 @ ff1_w + ff1_b)
        dim3 gF1(FFd / 64, Nn / 64, 1);
        gemm_kernel<64, 64, 4, 4, false, 1><<<gF1, 256>>>(
            p_xn, Dd, 0, ff1_w + (long long)l * Dd * FFd, FFd, 0,
            p_ff, FFd, 0, ff1_b + l * FFd, 0, nullptr, 1.f, Nn, FFd, Dd);

        // h += ff @ ff2_w + ff2_b
        dim3 gF2(Dd / 64, Nn / 64, 1);
        gemm_kernel<64, 64, 4, 4, false, 2><<<gF2, 256>>>(
            p_ff, FFd, 0, ff2_w + (long long)l * FFd * Dd, Dd, 0,
            p_h, Dd, 0, ff2_b + l * Dd, 0, nullptr, 1.f, Nn, Dd, FFd);
    }

    // out = h @ out_w + out_b   [2048,128] @ [128,64]
    dim3 gO(OUTd / 64, Nn / 64, 1);
    gemm_kernel<64, 64, 4, 4, false, 0><<<gO, 256>>>(
        p_h, Dd, 0, out_w, OUTd, 0,
        out, OUTd, 0, out_b, 0, nullptr, 1.f, Nn, OUTd, Dd);
}

// round 4
// speedup vs baseline: 1.6432x; 1.6432x over previous
#include <cuda_runtime.h>
#include <math.h>
#include <stdint.h>

// ---------------- problem constants ----------------
#define Nn   2048
#define Dd   128
#define Hh   8
#define FFd  512
#define OUTd 64
#define Ll   3
#define HSd  8
#define DEGMAX 64

// ---------------- device scratch (no allocations allowed) ----------------
__device__ float g_h[Nn * Dd];
__device__ float g_xn[Nn * Dd];
__device__ float g_bias[(size_t)Nn * Nn];
__device__ float g_q[Hh * Nn * Dd];
__device__ float g_k[Hh * Nn * Dd];
__device__ float g_v[Hh * Nn * Dd];
__device__ float g_scores[(size_t)Hh * Nn * Nn];
__device__ float g_o[Nn * Hh * Dd];
__device__ float g_ff[Nn * FFd];
__device__ int   g_indeg[Nn];
__device__ int   g_outdeg[Nn];

// ---------------- small kernels ----------------
__global__ void deg_zero_kernel() {
    int i = blockIdx.x * blockDim.x + threadIdx.x;
    if (i < Nn) { g_indeg[i] = 0; g_outdeg[i] = 0; }
}

__global__ void deg_count_kernel(const int* __restrict__ ei, int E) {
    int e = blockIdx.x * blockDim.x + threadIdx.x;
    if (e < E) {
        atomicAdd(&g_outdeg[ei[e]], 1);
        atomicAdd(&g_indeg[ei[E + e]], 1);
    }
}

__global__ void embed_kernel(const float* __restrict__ x, const float* __restrict__ W,
                             const float* __restrict__ b, const float* __restrict__ z_in,
                             const float* __restrict__ z_out) {
    int n = blockIdx.x, d = threadIdx.x;
    float acc = b[d];
#pragma unroll
    for (int i = 0; i < 16; i++) acc = fmaf(x[n * 16 + i], W[i * Dd + d], acc);
    int di = min(g_indeg[n],  DEGMAX - 1);
    int dn = min(g_outdeg[n], DEGMAX - 1);
    g_h[n * Dd + d] = acc + z_in[di * Dd + d] + z_out[dn * Dd + d];
}

__global__ void spbias_kernel(const float* __restrict__ pos, const float* __restrict__ mu,
                              const float* __restrict__ sigma, const float* __restrict__ w,
                              const float* __restrict__ b0) {
    long long idx = (long long)blockIdx.x * blockDim.x + threadIdx.x;
    int i = (int)(idx / Nn), j = (int)(idx % Nn);
    float dx = pos[i * 3 + 0] - pos[j * 3 + 0];
    float dy = pos[i * 3 + 1] - pos[j * 3 + 1];
    float dz = pos[i * 3 + 2] - pos[j * 3 + 2];
    float d = sqrtf(dx * dx + dy * dy + dz * dz + 1e-12f);
    float acc = b0[0];
#pragma unroll
    for (int t = 0; t < HSd; t++) {
        float u = (d - mu[t]) / sigma[t];
        acc = fmaf(__expf(-0.5f * u * u), w[t], acc);
    }
    g_bias[idx] = acc;
}

__global__ void ln_kernel(const float* __restrict__ x, float* __restrict__ y,
                          const float* __restrict__ g, const float* __restrict__ b) {
    int n = blockIdx.x, t = threadIdx.x;
    float v = x[n * Dd + t];
    float s = v, sq = v * v;
#pragma unroll
    for (int o = 16; o > 0; o >>= 1) {
        s  += __shfl_xor_sync(0xffffffffu, s,  o);
        sq += __shfl_xor_sync(0xffffffffu, sq, o);
    }
    __shared__ float ss[4], ssq[4];
    if ((t & 31) == 0) { ss[t >> 5] = s; ssq[t >> 5] = sq; }
    __syncthreads();
    float S = ss[0] + ss[1] + ss[2] + ss[3];
    float Q = ssq[0] + ssq[1] + ssq[2] + ssq[3];
    float mean = S * (1.0f / Dd);
    float var  = Q * (1.0f / Dd) - mean * mean;
    y[n * Dd + t] = (v - mean) * rsqrtf(var + 1e-5f) * g[t] + b[t];
}

__global__ void __launch_bounds__(256) softmax_kernel(float* __restrict__ Sbase) {
    float* row = Sbase + (long long)blockIdx.x * Nn;
    int t = threadIdx.x;
    float4 v0 = *reinterpret_cast<const float4*>(row + t * 4);
    float4 v1 = *reinterpret_cast<const float4*>(row + 1024 + t * 4);
    float m = fmaxf(fmaxf(fmaxf(v0.x, v0.y), fmaxf(v0.z, v0.w)),
                    fmaxf(fmaxf(v1.x, v1.y), fmaxf(v1.z, v1.w)));
#pragma unroll
    for (int o = 16; o > 0; o >>= 1) m = fmaxf(m, __shfl_xor_sync(0xffffffffu, m, o));
    __shared__ float sm[8];
    if ((t & 31) == 0) sm[t >> 5] = m;
    __syncthreads();
    m = fmaxf(fmaxf(fmaxf(sm[0], sm[1]), fmaxf(sm[2], sm[3])),
              fmaxf(fmaxf(sm[4], sm[5]), fmaxf(sm[6], sm[7])));

    v0.x = __expf(v0.x - m); v0.y = __expf(v0.y - m);
    v0.z = __expf(v0.z - m); v0.w = __expf(v0.w - m);
    v1.x = __expf(v1.x - m); v1.y = __expf(v1.y - m);
    v1.z = __expf(v1.z - m); v1.w = __expf(v1.w - m);
    float s = v0.x + v0.y + v0.z + v0.w + v1.x + v1.y + v1.z + v1.w;
#pragma unroll
    for (int o = 16; o > 0; o >>= 1) s += __shfl_xor_sync(0xffffffffu, s, o);
    __shared__ float sw[8];
    if ((t & 31) == 0) sw[t >> 5] = s;
    __syncthreads();
    s = sw[0] + sw[1] + sw[2] + sw[3] + sw[4] + sw[5] + sw[6] + sw[7];
    float inv = 1.0f / s;
    v0.x *= inv; v0.y *= inv; v0.z *= inv; v0.w *= inv;
    v1.x *= inv; v1.y *= inv; v1.z *= inv; v1.w *= inv;
    *reinterpret_cast<float4*>(row + t * 4) = v0;
    *reinterpret_cast<float4*>(row + 1024 + t * 4) = v1;
}

// ---------------- tf32 tensor-core GEMM ----------------
// C[M,Nc] = epi( A[M,K] * (TB ? B[Nc,K]^T : B[K,Nc]) )
// EPI: 0=+bias[col]  1=gelu(+bias[col])  2=C+=acc+bias[col]  3=acc*alpha+bias2d  4=plain
// 256 threads, warp grid 2x4, warp tile (BM/2)x(BN/4), BK=32.
// Requires M%BM==0, Nc%BN==0, K%32==0.

__device__ __forceinline__ uint32_t f2tf32(float f) {
    uint32_t r;
    asm("cvt.rna.tf32.f32 %0, %1;" : "=r"(r) : "f"(f));
    return r;
}

template <int BM, int BN, bool TB, int EPI>
__global__ void __launch_bounds__(256, 2)
gemm_tf32(const float* __restrict__ A, int lda, long long sA,
          const float* __restrict__ B, int ldb, long long sB,
          float* __restrict__ C, int ldc, long long sC,
          const float* __restrict__ bias, int sBias,
          const float* __restrict__ bias2d,
          float alpha, int M, int Nc, int K)
{
    constexpr int BK  = 32;
    constexpr int LDA = BM + 8;      // smem strides chosen for conflict-free frag loads
    constexpr int LDB = BN + 8;
    constexpr int MI  = BM / 32;     // m-frags per warp
    constexpr int NI  = BN / 32;     // n-frags per warp

    const int z = blockIdx.z;
    A += (long long)z * sA;
    B += (long long)z * sB;
    C += (long long)z * sC;
    if (EPI == 0 || EPI == 1 || EPI == 2) bias += (long long)z * sBias;

    __shared__ uint32_t As[BK * LDA];   // [k][m]
    __shared__ uint32_t Bs[BK * LDB];   // [k][n]

    const int tid  = threadIdx.x;
    const int wid  = tid >> 5;
    const int lane = tid & 31;
    const int gid  = lane >> 2;      // 0..7
    const int tid4 = lane & 3;       // 0..3
    const int warpM = wid & 1;       // 0..1
    const int warpN = wid >> 1;      // 0..3
    const int rowBase = blockIdx.y * BM;
    const int colBase = blockIdx.x * BN;

    float acc[MI][NI][4];
#pragma unroll
    for (int mi = 0; mi < MI; mi++)
#pragma unroll
        for (int ni = 0; ni < NI; ni++)
#pragma unroll
            for (int r = 0; r < 4; r++) acc[mi][ni][r] = 0.f;

    for (int k0 = 0; k0 < K; k0 += BK) {
        // --- stage A (k-outer layout, tf32-converted) ---
#pragma unroll
        for (int it = 0; it < (BM * BK) / 1024; it++) {
            int idx = (tid + it * 256) * 4;          // k-fastest within row
            int r  = idx / BK;
            int kk = idx % BK;
            float4 av = *reinterpret_cast<const float4*>(
                &A[(long long)(rowBase + r) * lda + k0 + kk]);
            As[(kk + 0) * LDA + r] = f2tf32(av.x);
            As[(kk + 1) * LDA + r] = f2tf32(av.y);
            As[(kk + 2) * LDA + r] = f2tf32(av.z);
            As[(kk + 3) * LDA + r] = f2tf32(av.w);
        }
        // --- stage B ---
        if (TB) {
#pragma unroll
            for (int it = 0; it < (BN * BK) / 1024; it++) {
                int idx = (tid + it * 256) * 4;      // k-fastest within col
                int c  = idx / BK;
                int kk = idx % BK;
                float4 bv = *reinterpret_cast<const float4*>(
                    &B[(long long)(colBase + c) * ldb + k0 + kk]);
                Bs[(kk + 0) * LDB + c] = f2tf32(bv.x);
                Bs[(kk + 1) * LDB + c] = f2tf32(bv.y);
                Bs[(kk + 2) * LDB + c] = f2tf32(bv.z);
                Bs[(kk + 3) * LDB + c] = f2tf32(bv.w);
            }
        } else {
#pragma unroll
            for (int it = 0; it < (BN * BK) / 1024; it++) {
                int idx = (tid + it * 256) * 4;      // n-fastest within k-row
                int kr = idx / BN;
                int c  = idx % BN;
                float4 bv = *reinterpret_cast<const float4*>(
                    &B[(long long)(k0 + kr) * ldb + colBase + c]);
                uint4 o;
                o.x = f2tf32(bv.x); o.y = f2tf32(bv.y);
                o.z = f2tf32(bv.z); o.w = f2tf32(bv.w);
                *reinterpret_cast<uint4*>(&Bs[kr * LDB + c]) = o;
            }
        }
        __syncthreads();

        // --- compute: 4 k-steps of 8 ---
#pragma unroll
        for (int ks = 0; ks < 4; ks++) {
            const int kk = ks * 8;
            uint32_t a[MI][4];
#pragma unroll
            for (int mi = 0; mi < MI; mi++) {
                int r = warpM * (BM / 2) + mi * 16 + gid;
                a[mi][0] = As[(kk + tid4) * LDA + r];
                a[mi][1] = As[(kk + tid4) * LDA + r + 8];
                a[mi][2] = As[(kk + tid4 + 4) * LDA + r];
                a[mi][3] = As[(kk + tid4 + 4) * LDA + r + 8];
            }
            uint32_t b[NI][2];
#pragma unroll
            for (int ni = 0; ni < NI; ni++) {
                int col = warpN * (BN / 4) + ni * 8 + gid;
                b[ni][0] = Bs[(kk + tid4) * LDB + col];
                b[ni][1] = Bs[(kk + tid4 + 4) * LDB + col];
            }
#pragma unroll
            for (int mi = 0; mi < MI; mi++)
#pragma unroll
                for (int ni = 0; ni < NI; ni++) {
                    asm volatile(
                        "mma.sync.aligned.m16n8k8.row.col.f32.tf32.tf32.f32 "
                        "{%0,%1,%2,%3}, {%4,%5,%6,%7}, {%8,%9}, {%0,%1,%2,%3};"
                        : "+f"(acc[mi][ni][0]), "+f"(acc[mi][ni][1]),
                          "+f"(acc[mi][ni][2]), "+f"(acc[mi][ni][3])
                        : "r"(a[mi][0]), "r"(a[mi][1]), "r"(a[mi][2]), "r"(a[mi][3]),
                          "r"(b[ni][0]), "r"(b[ni][1]));
                }
        }
        __syncthreads();
    }

    // --- epilogue ---
#pragma unroll
    for (int mi = 0; mi < MI; mi++) {
#pragma unroll
        for (int ni = 0; ni < NI; ni++) {
#pragma unroll
            for (int half = 0; half < 2; half++) {
                int row = rowBase + warpM * (BM / 2) + mi * 16 + gid + half * 8;
                int col = colBase + warpN * (BN / 4) + ni * 8 + tid4 * 2;
                float v0 = acc[mi][ni][half * 2 + 0];
                float v1 = acc[mi][ni][half * 2 + 1];
                long long ci = (long long)row * ldc + col;
                if (EPI == 0) {
                    C[ci]     = v0 + bias[col];
                    C[ci + 1] = v1 + bias[col + 1];
                } else if (EPI == 1) {
                    v0 += bias[col];
                    v1 += bias[col + 1];
                    C[ci]     = 0.5f * v0 * (1.0f + erff(v0 * 0.70710678118654752f));
                    C[ci + 1] = 0.5f * v1 * (1.0f + erff(v1 * 0.70710678118654752f));
                } else if (EPI == 2) {
                    C[ci]     += v0 + bias[col];
                    C[ci + 1] += v1 + bias[col + 1];
                } else if (EPI == 3) {
                    long long bi = (long long)row * Nc + col;
                    C[ci]     = v0 * alpha + bias2d[bi];
                    C[ci + 1] = v1 * alpha + bias2d[bi + 1];
                } else {
                    C[ci]     = v0;
                    C[ci + 1] = v1;
                }
            }
        }
    }
}

// ---------------- launcher ----------------
extern "C" void kernel_launch(void* const* d_in, const int* in_sizes, int n_in,
                              void* d_out, int out_size)
{
    (void)n_in; (void)out_size;
    const float* x         = (const float*)d_in[0];
    const int*   ei        = (const int*)  d_in[1];
    const float* pos       = (const float*)d_in[3];
    const float* node_in_w = (const float*)d_in[4];
    const float* node_in_b = (const float*)d_in[5];
    const float* z_in      = (const float*)d_in[8];
    const float* z_out     = (const float*)d_in[9];
    const float* sp_mu     = (const float*)d_in[10];
    const float* sp_sigma  = (const float*)d_in[11];
    const float* sp_w      = (const float*)d_in[12];
    const float* sp_b      = (const float*)d_in[13];
    const float* Wq        = (const float*)d_in[14];
    const float* bq        = (const float*)d_in[15];
    const float* Wk        = (const float*)d_in[16];
    const float* bk        = (const float*)d_in[17];
    const float* Wv        = (const float*)d_in[18];
    const float* bv        = (const float*)d_in[19];
    const float* Wo        = (const float*)d_in[20];
    const float* bo        = (const float*)d_in[21];
    const float* ln1_g     = (const float*)d_in[22];
    const float* ln1_b     = (const float*)d_in[23];
    const float* ln2_g     = (const float*)d_in[24];
    const float* ln2_b     = (const float*)d_in[25];
    const float* ff1_w     = (const float*)d_in[26];
    const float* ff1_b     = (const float*)d_in[27];
    const float* ff2_w     = (const float*)d_in[28];
    const float* ff2_b     = (const float*)d_in[29];
    const float* out_w     = (const float*)d_in[30];
    const float* out_b     = (const float*)d_in[31];
    float* out = (float*)d_out;

    const int E = in_sizes[1] / 2;
    const float scale = 0.08838834764831845f;  // 1/sqrt(128)

    float *p_h, *p_xn, *p_bias, *p_q, *p_k, *p_v, *p_s, *p_o, *p_ff;
    cudaGetSymbolAddress((void**)&p_h,    g_h);
    cudaGetSymbolAddress((void**)&p_xn,   g_xn);
    cudaGetSymbolAddress((void**)&p_bias, g_bias);
    cudaGetSymbolAddress((void**)&p_q,    g_q);
    cudaGetSymbolAddress((void**)&p_k,    g_k);
    cudaGetSymbolAddress((void**)&p_v,    g_v);
    cudaGetSymbolAddress((void**)&p_s,    g_scores);
    cudaGetSymbolAddress((void**)&p_o,    g_o);
    cudaGetSymbolAddress((void**)&p_ff,   g_ff);

    deg_zero_kernel<<<(Nn + 255) / 256, 256>>>();
    deg_count_kernel<<<(E + 255) / 256, 256>>>(ei, E);
    embed_kernel<<<Nn, Dd>>>(x, node_in_w, node_in_b, z_in, z_out);
    spbias_kernel<<<(int)(((long long)Nn * Nn) / 256), 256>>>(pos, sp_mu, sp_sigma, sp_w, sp_b);

    const long long sHead = (long long)Nn * Dd;
    const long long sW    = (long long)Dd * Dd;
    const long long sS    = (long long)Nn * Nn;

    for (int l = 0; l < Ll; l++) {
        ln_kernel<<<Nn, Dd>>>(p_h, p_xn, ln1_g + l * Dd, ln1_b + l * Dd);

        // QKV projections (batched over heads): [2048,128] @ [128,128] + bias
        dim3 gQ(Dd / 128, Nn / 128, Hh);
        gemm_tf32<128, 128, false, 0><<<gQ, 256>>>(
            p_xn, Dd, 0, Wq + (long long)l * Hh * sW, Dd, sW,
            p_q, Dd, sHead, bq + (long long)l * Hh * Dd, Dd, nullptr, 1.f, Nn, Dd, Dd);
        gemm_tf32<128, 128, false, 0><<<gQ, 256>>>(
            p_xn, Dd, 0, Wk + (long long)l * Hh * sW, Dd, sW,
            p_k, Dd, sHead, bk + (long long)l * Hh * Dd, Dd, nullptr, 1.f, Nn, Dd, Dd);
        gemm_tf32<128, 128, false, 0><<<gQ, 256>>>(
            p_xn, Dd, 0, Wv + (long long)l * Hh * sW, Dd, sW,
            p_v, Dd, sHead, bv + (long long)l * Hh * Dd, Dd, nullptr, 1.f, Nn, Dd, Dd);

        // scores = q @ k^T * scale + bias   [8][2048,2048]
        dim3 gS(Nn / 128, Nn / 128, Hh);
        gemm_tf32<128, 128, true, 3><<<gS, 256>>>(
            p_q, Dd, sHead, p_k, Dd, sHead,
            p_s, Nn, sS, nullptr, 0, p_bias, scale, Nn, Nn, Dd);

        softmax_kernel<<<Hh * Nn, 256>>>(p_s);

        // o = attn @ v  (BN=64 for occupancy: 256 blocks)
        dim3 gA(Dd / 64, Nn / 128, Hh);
        gemm_tf32<128, 64, false, 4><<<gA, 256>>>(
            p_s, Nn, sS, p_v, Dd, sHead,
            p_o, Hh * Dd, Dd, nullptr, 0, nullptr, 1.f, Nn, Dd, Nn);

        // h += o @ Wo + bo   (K=1024, 64 blocks)
        dim3 gW2(Dd / 64, Nn / 64, 1);
        gemm_tf32<64, 64, false, 2><<<gW2, 256>>>(
            p_o, Hh * Dd, 0, Wo + (long long)l * Hh * Dd * Dd, Dd, 0,
            p_h, Dd, 0, bo + l * Dd, 0, nullptr, 1.f, Nn, Dd, Hh * Dd);

        ln_kernel<<<Nn, Dd>>>(p_h, p_xn, ln2_g + l * Dd, ln2_b + l * Dd);

        // ff = gelu(xn2 @ ff1_w + ff1_b)
        dim3 gF1(FFd / 128, Nn / 128, 1);
        gemm_tf32<128, 128, false, 1><<<gF1, 256>>>(
            p_xn, Dd, 0, ff1_w + (long long)l * Dd * FFd, FFd, 0,
            p_ff, FFd, 0, ff1_b + l * FFd, 0, nullptr, 1.f, Nn, FFd, Dd);

        // h += ff @ ff2_w + ff2_b   (K=512)
        dim3 gF2(Dd / 64, Nn / 64, 1);
        gemm_tf32<64, 64, false, 2><<<gF2, 256>>>(
            p_ff, FFd, 0, ff2_w + (long long)l * FFd * Dd, Dd, 0,
            p_h, Dd, 0, ff2_b + l * Dd, 0, nullptr, 1.f, Nn, Dd, FFd);
    }

    // out = h @ out_w + out_b   [2048,128] @ [128,64]
    dim3 gO(OUTd / 64, Nn / 64, 1);
    gemm_tf32<64, 64, false, 0><<<gO, 256>>>(
        p_h, Dd, 0, out_w, OUTd, 0,
        out, OUTd, 0, out_b, 0, nullptr, 1.f, Nn, OUTd, Dd);
}

// round 5
// speedup vs baseline: 2.8977x; 1.7634x over previous
#include <cuda_runtime.h>
#include <math.h>
#include <stdint.h>

// ---------------- problem constants ----------------
#define Nn   2048
#define Dd   128
#define Hh   8
#define FFd  512
#define OUTd 64
#define Ll   3
#define HSd  8
#define DEGMAX 64

// ---------------- device scratch (no allocations allowed) ----------------
__device__ float g_h[Nn * Dd];
__device__ float g_xn[Nn * Dd];
__device__ float g_bias[(size_t)Nn * Nn];
__device__ float g_q[Hh * Nn * Dd];
__device__ float g_k[Hh * Nn * Dd];
__device__ float g_v[Hh * Nn * Dd];
__device__ float g_o[Nn * Hh * Dd];
__device__ float g_ff[Nn * FFd];
__device__ int   g_indeg[Nn];
__device__ int   g_outdeg[Nn];

// ---------------- small kernels ----------------
__global__ void deg_zero_kernel() {
    int i = blockIdx.x * blockDim.x + threadIdx.x;
    if (i < Nn) { g_indeg[i] = 0; g_outdeg[i] = 0; }
}

__global__ void deg_count_kernel(const int* __restrict__ ei, int E) {
    int e = blockIdx.x * blockDim.x + threadIdx.x;
    if (e < E) {
        atomicAdd(&g_outdeg[ei[e]], 1);
        atomicAdd(&g_indeg[ei[E + e]], 1);
    }
}

__global__ void embed_kernel(const float* __restrict__ x, const float* __restrict__ W,
                             const float* __restrict__ b, const float* __restrict__ z_in,
                             const float* __restrict__ z_out) {
    int n = blockIdx.x, d = threadIdx.x;
    float acc = b[d];
#pragma unroll
    for (int i = 0; i < 16; i++) acc = fmaf(x[n * 16 + i], W[i * Dd + d], acc);
    int di = min(g_indeg[n],  DEGMAX - 1);
    int dn = min(g_outdeg[n], DEGMAX - 1);
    g_h[n * Dd + d] = acc + z_in[di * Dd + d] + z_out[dn * Dd + d];
}

__global__ void spbias_kernel(const float* __restrict__ pos, const float* __restrict__ mu,
                              const float* __restrict__ sigma, const float* __restrict__ w,
                              const float* __restrict__ b0) {
    long long idx = (long long)blockIdx.x * blockDim.x + threadIdx.x;
    int i = (int)(idx / Nn), j = (int)(idx % Nn);
    float dx = pos[i * 3 + 0] - pos[j * 3 + 0];
    float dy = pos[i * 3 + 1] - pos[j * 3 + 1];
    float dz = pos[i * 3 + 2] - pos[j * 3 + 2];
    float d = sqrtf(dx * dx + dy * dy + dz * dz + 1e-12f);
    float acc = b0[0];
#pragma unroll
    for (int t = 0; t < HSd; t++) {
        float u = (d - mu[t]) / sigma[t];
        acc = fmaf(__expf(-0.5f * u * u), w[t], acc);
    }
    g_bias[idx] = acc;
}

__global__ void ln_kernel(const float* __restrict__ x, float* __restrict__ y,
                          const float* __restrict__ g, const float* __restrict__ b) {
    int n = blockIdx.x, t = threadIdx.x;
    float v = x[n * Dd + t];
    float s = v, sq = v * v;
#pragma unroll
    for (int o = 16; o > 0; o >>= 1) {
        s  += __shfl_xor_sync(0xffffffffu, s,  o);
        sq += __shfl_xor_sync(0xffffffffu, sq, o);
    }
    __shared__ float ss[4], ssq[4];
    if ((t & 31) == 0) { ss[t >> 5] = s; ssq[t >> 5] = sq; }
    __syncthreads();
    float S = ss[0] + ss[1] + ss[2] + ss[3];
    float Q = ssq[0] + ssq[1] + ssq[2] + ssq[3];
    float mean = S * (1.0f / Dd);
    float var  = Q * (1.0f / Dd) - mean * mean;
    y[n * Dd + t] = (v - mean) * rsqrtf(var + 1e-5f) * g[t] + b[t];
}

__device__ __forceinline__ uint32_t f2tf32(float f) {
    uint32_t r;
    asm("cvt.rna.tf32.f32 %0, %1;" : "=r"(r) : "f"(f));
    return r;
}

// ---------------- fused flash attention (tf32 mma) ----------------
// One block per (128-query tile, head). 256 threads, warp grid 2x4.
// smem: Qs [128 q][132 d], Ps [128][132] (K tile then P tile), Vs [128 key][136 d],
//       redM/redS [128][4].
__global__ void __launch_bounds__(256, 1)
flash_kernel(const float* __restrict__ Qg, const float* __restrict__ Kg,
             const float* __restrict__ Vg, const float* __restrict__ Bias,
             float* __restrict__ Og, float scale)
{
    extern __shared__ uint32_t sh[];
    uint32_t* Qs = sh;                       // 128*132
    uint32_t* Ps = sh + 128 * 132;           // 128*132 (K, later P)
    uint32_t* Vs = sh + 2 * 128 * 132;       // 128*136
    float* redM = (float*)(sh + 2 * 128 * 132 + 128 * 136);   // [128][4]
    float* redS = redM + 512;                                  // [128][4]

    const int tid  = threadIdx.x;
    const int wid  = tid >> 5, lane = tid & 31;
    const int gid  = lane >> 2, tid4 = lane & 3;
    const int warpM = wid & 1, warpN = wid >> 1;
    const int qBase = blockIdx.x * 128;
    const int head  = blockIdx.y;
    const int r0 = warpM * 64;
    const int c0 = warpN * 32;

    const float* Qh = Qg + (long long)head * Nn * Dd;
    const float* Kh = Kg + (long long)head * Nn * Dd;
    const float* Vh = Vg + (long long)head * Nn * Dd;

    // stage Q tile (row-major [q][d], uint4 stores -> 4 clean phases)
#pragma unroll
    for (int it = 0; it < 16; it++) {
        int idx = (tid + it * 256) * 4;
        int r = idx >> 7, kk = idx & 127;
        float4 av = *reinterpret_cast<const float4*>(&Qh[(long long)(qBase + r) * Dd + kk]);
        uint4 o4; o4.x = f2tf32(av.x); o4.y = f2tf32(av.y);
        o4.z = f2tf32(av.z); o4.w = f2tf32(av.w);
        *reinterpret_cast<uint4*>(&Qs[r * 132 + kk]) = o4;
    }

    float accO[4][4][4];
#pragma unroll
    for (int mi = 0; mi < 4; mi++)
#pragma unroll
        for (int ni = 0; ni < 4; ni++)
#pragma unroll
            for (int r = 0; r < 4; r++) accO[mi][ni][r] = 0.f;
    float mrow[4][2], lrow[4][2];
#pragma unroll
    for (int mi = 0; mi < 4; mi++) {
        mrow[mi][0] = -1e30f; mrow[mi][1] = -1e30f;
        lrow[mi][0] = 0.f;    lrow[mi][1] = 0.f;
    }

    for (int j = 0; j < 16; j++) {
        const int kBase = j * 128;
        // stage K tile into Ps (row-major [key][d])
#pragma unroll
        for (int it = 0; it < 16; it++) {
            int idx = (tid + it * 256) * 4;
            int c = idx >> 7, kk = idx & 127;
            float4 bv = *reinterpret_cast<const float4*>(&Kh[(long long)(kBase + c) * Dd + kk]);
            uint4 o4; o4.x = f2tf32(bv.x); o4.y = f2tf32(bv.y);
            o4.z = f2tf32(bv.z); o4.w = f2tf32(bv.w);
            *reinterpret_cast<uint4*>(&Ps[c * 132 + kk]) = o4;
        }
        // stage V tile (row-major [key][d], LD=136 for conflict-free b-frag reads)
#pragma unroll
        for (int it = 0; it < 16; it++) {
            int idx = (tid + it * 256) * 4;
            int kr = idx >> 7, c = idx & 127;
            float4 bv = *reinterpret_cast<const float4*>(&Vh[(long long)(kBase + kr) * Dd + c]);
            uint4 o4; o4.x = f2tf32(bv.x); o4.y = f2tf32(bv.y);
            o4.z = f2tf32(bv.z); o4.w = f2tf32(bv.w);
            *reinterpret_cast<uint4*>(&Vs[kr * 136 + c]) = o4;
        }
        __syncthreads();

        // ---- S = Q . K^T ----
        float accS[4][4][4];
#pragma unroll
        for (int mi = 0; mi < 4; mi++)
#pragma unroll
            for (int ni = 0; ni < 4; ni++)
#pragma unroll
                for (int r = 0; r < 4; r++) accS[mi][ni][r] = 0.f;
#pragma unroll
        for (int ks = 0; ks < 16; ks++) {
            const int kk = ks * 8;
            uint32_t a[4][4], b[4][2];
#pragma unroll
            for (int mi = 0; mi < 4; mi++) {
                int r = r0 + mi * 16 + gid;
                a[mi][0] = Qs[r * 132 + kk + tid4];
                a[mi][1] = Qs[(r + 8) * 132 + kk + tid4];
                a[mi][2] = Qs[r * 132 + kk + tid4 + 4];
                a[mi][3] = Qs[(r + 8) * 132 + kk + tid4 + 4];
            }
#pragma unroll
            for (int ni = 0; ni < 4; ni++) {
                int col = c0 + ni * 8 + gid;
                b[ni][0] = Ps[col * 132 + kk + tid4];
                b[ni][1] = Ps[col * 132 + kk + tid4 + 4];
            }
#pragma unroll
            for (int mi = 0; mi < 4; mi++)
#pragma unroll
                for (int ni = 0; ni < 4; ni++) {
                    asm volatile(
                        "mma.sync.aligned.m16n8k8.row.col.f32.tf32.tf32.f32 "
                        "{%0,%1,%2,%3}, {%4,%5,%6,%7}, {%8,%9}, {%0,%1,%2,%3};"
                        : "+f"(accS[mi][ni][0]), "+f"(accS[mi][ni][1]),
                          "+f"(accS[mi][ni][2]), "+f"(accS[mi][ni][3])
                        : "r"(a[mi][0]), "r"(a[mi][1]), "r"(a[mi][2]), "r"(a[mi][3]),
                          "r"(b[ni][0]), "r"(b[ni][1]));
                }
        }
        __syncthreads();   // all warps done reading K before P overwrites Ps

        // ---- scale + bias, per-warp row-max partials ----
#pragma unroll
        for (int mi = 0; mi < 4; mi++) {
#pragma unroll
            for (int half = 0; half < 2; half++) {
                int rl = r0 + mi * 16 + gid + half * 8;
                long long brow = (long long)(qBase + rl) * Nn + kBase;
                float rmax = -1e30f;
#pragma unroll
                for (int ni = 0; ni < 4; ni++) {
                    int cl = c0 + ni * 8 + tid4 * 2;
                    float2 bb = *reinterpret_cast<const float2*>(&Bias[brow + cl]);
                    float s0 = accS[mi][ni][half * 2 + 0] * scale + bb.x;
                    float s1 = accS[mi][ni][half * 2 + 1] * scale + bb.y;
                    accS[mi][ni][half * 2 + 0] = s0;
                    accS[mi][ni][half * 2 + 1] = s1;
                    rmax = fmaxf(rmax, fmaxf(s0, s1));
                }
                rmax = fmaxf(rmax, __shfl_xor_sync(0xffffffffu, rmax, 1));
                rmax = fmaxf(rmax, __shfl_xor_sync(0xffffffffu, rmax, 2));
                if (tid4 == 0) redM[rl * 4 + warpN] = rmax;
            }
        }
        __syncthreads();

        // ---- m/l update, p = exp, rescale O, write P ----
#pragma unroll
        for (int mi = 0; mi < 4; mi++) {
#pragma unroll
            for (int half = 0; half < 2; half++) {
                int rl = r0 + mi * 16 + gid + half * 8;
                float tm = fmaxf(fmaxf(redM[rl * 4 + 0], redM[rl * 4 + 1]),
                                 fmaxf(redM[rl * 4 + 2], redM[rl * 4 + 3]));
                float mold = mrow[mi][half];
                float mnew = fmaxf(mold, tm);
                float fac  = __expf(mold - mnew);
                mrow[mi][half] = mnew;
                lrow[mi][half] *= fac;
                float psum = 0.f;
#pragma unroll
                for (int ni = 0; ni < 4; ni++) {
                    float p0 = __expf(accS[mi][ni][half * 2 + 0] - mnew);
                    float p1 = __expf(accS[mi][ni][half * 2 + 1] - mnew);
                    accS[mi][ni][half * 2 + 0] = p0;
                    accS[mi][ni][half * 2 + 1] = p1;
                    psum += p0 + p1;
                    accO[mi][ni][half * 2 + 0] *= fac;
                    accO[mi][ni][half * 2 + 1] *= fac;
                }
                psum += __shfl_xor_sync(0xffffffffu, psum, 1);
                psum += __shfl_xor_sync(0xffffffffu, psum, 2);
                if (tid4 == 0) redS[rl * 4 + warpN] = psum;
            }
        }
        // write P (row-major [q][key]) into Ps
#pragma unroll
        for (int mi = 0; mi < 4; mi++)
#pragma unroll
            for (int half = 0; half < 2; half++) {
                int rl = r0 + mi * 16 + gid + half * 8;
#pragma unroll
                for (int ni = 0; ni < 4; ni++) {
                    int cl = c0 + ni * 8 + tid4 * 2;
                    Ps[rl * 132 + cl]     = f2tf32(accS[mi][ni][half * 2 + 0]);
                    Ps[rl * 132 + cl + 1] = f2tf32(accS[mi][ni][half * 2 + 1]);
                }
            }
        __syncthreads();

        // accumulate tile row-sums into l
#pragma unroll
        for (int mi = 0; mi < 4; mi++)
#pragma unroll
            for (int half = 0; half < 2; half++) {
                int rl = r0 + mi * 16 + gid + half * 8;
                lrow[mi][half] += redS[rl * 4 + 0] + redS[rl * 4 + 1]
                                + redS[rl * 4 + 2] + redS[rl * 4 + 3];
            }

        // ---- O += P . V ----
#pragma unroll
        for (int ks = 0; ks < 16; ks++) {
            const int kk = ks * 8;
            uint32_t a[4][4], b[4][2];
#pragma unroll
            for (int mi = 0; mi < 4; mi++) {
                int r = r0 + mi * 16 + gid;
                a[mi][0] = Ps[r * 132 + kk + tid4];
                a[mi][1] = Ps[(r + 8) * 132 + kk + tid4];
                a[mi][2] = Ps[r * 132 + kk + tid4 + 4];
                a[mi][3] = Ps[(r + 8) * 132 + kk + tid4 + 4];
            }
#pragma unroll
            for (int ni = 0; ni < 4; ni++) {
                int col = c0 + ni * 8 + gid;
                b[ni][0] = Vs[(kk + tid4) * 136 + col];
                b[ni][1] = Vs[(kk + tid4 + 4) * 136 + col];
            }
#pragma unroll
            for (int mi = 0; mi < 4; mi++)
#pragma unroll
                for (int ni = 0; ni < 4; ni++) {
                    asm volatile(
                        "mma.sync.aligned.m16n8k8.row.col.f32.tf32.tf32.f32 "
                        "{%0,%1,%2,%3}, {%4,%5,%6,%7}, {%8,%9}, {%0,%1,%2,%3};"
                        : "+f"(accO[mi][ni][0]), "+f"(accO[mi][ni][1]),
                          "+f"(accO[mi][ni][2]), "+f"(accO[mi][ni][3])
                        : "r"(a[mi][0]), "r"(a[mi][1]), "r"(a[mi][2]), "r"(a[mi][3]),
                          "r"(b[ni][0]), "r"(b[ni][1]));
                }
        }
        __syncthreads();   // before next iteration restages Ps/Vs
    }

    // ---- epilogue: O / l -> g_o[q][head*128+d] ----
#pragma unroll
    for (int mi = 0; mi < 4; mi++)
#pragma unroll
        for (int half = 0; half < 2; half++) {
            int rl = r0 + mi * 16 + gid + half * 8;
            float inv = 1.0f / lrow[mi][half];
#pragma unroll
            for (int ni = 0; ni < 4; ni++) {
                int cl = c0 + ni * 8 + tid4 * 2;
                float2 ov;
                ov.x = accO[mi][ni][half * 2 + 0] * inv;
                ov.y = accO[mi][ni][half * 2 + 1] * inv;
                *reinterpret_cast<float2*>(
                    &Og[(long long)(qBase + rl) * (Hh * Dd) + head * Dd + cl]) = ov;
            }
        }
}

// ---------------- tf32 tensor-core GEMM (conflict-free staging) ----------------
// C[M,Nc] = epi( A[M,K] * (TB ? B[Nc,K]^T : B[K,Nc]) )
// EPI: 0=+bias[col]  1=gelu(+bias[col])  2=C+=acc+bias[col]  4=plain
template <int BM, int BN, bool TB, int EPI>
__global__ void __launch_bounds__(256, 2)
gemm_tf32(const float* __restrict__ A, int lda, long long sA,
          const float* __restrict__ B, int ldb, long long sB,
          float* __restrict__ C, int ldc, long long sC,
          const float* __restrict__ bias, int sBias,
          int M, int Nc, int K)
{
    constexpr int BK   = 32;
    constexpr int LDAr = BK + 4;                       // row-major A [BM][36]
    constexpr int LDBr = TB ? (BK + 4) : (BN + 8);
    constexpr int BSZ  = TB ? BN * LDBr : BK * LDBr;
    constexpr int MI   = BM / 32;
    constexpr int NI   = BN / 32;

    const int z = blockIdx.z;
    A += (long long)z * sA;
    B += (long long)z * sB;
    C += (long long)z * sC;
    if (EPI == 0 || EPI == 1 || EPI == 2) bias += (long long)z * sBias;

    __shared__ uint32_t As[BM * LDAr];
    __shared__ uint32_t Bs[BSZ];

    const int tid  = threadIdx.x;
    const int wid  = tid >> 5;
    const int lane = tid & 31;
    const int gid  = lane >> 2;
    const int tid4 = lane & 3;
    const int warpM = wid & 1;
    const int warpN = wid >> 1;
    const int rowBase = blockIdx.y * BM;
    const int colBase = blockIdx.x * BN;

    float acc[MI][NI][4];
#pragma unroll
    for (int mi = 0; mi < MI; mi++)
#pragma unroll
        for (int ni = 0; ni < NI; ni++)
#pragma unroll
            for (int r = 0; r < 4; r++) acc[mi][ni][r] = 0.f;

    for (int k0 = 0; k0 < K; k0 += BK) {
#pragma unroll
        for (int it = 0; it < (BM * BK) / 1024; it++) {
            int idx = (tid + it * 256) * 4;
            int r  = idx / BK;
            int kk = idx % BK;
            float4 av = *reinterpret_cast<const float4*>(
                &A[(long long)(rowBase + r) * lda + k0 + kk]);
            uint4 o4; o4.x = f2tf32(av.x); o4.y = f2tf32(av.y);
            o4.z = f2tf32(av.z); o4.w = f2tf32(av.w);
            *reinterpret_cast<uint4*>(&As[r * LDAr + kk]) = o4;
        }
        if (TB) {
#pragma unroll
            for (int it = 0; it < (BN * BK) / 1024; it++) {
                int idx = (tid + it * 256) * 4;
                int c  = idx / BK;
                int kk = idx % BK;
                float4 bv = *reinterpret_cast<const float4*>(
                    &B[(long long)(colBase + c) * ldb + k0 + kk]);
                uint4 o4; o4.x = f2tf32(bv.x); o4.y = f2tf32(bv.y);
                o4.z = f2tf32(bv.z); o4.w = f2tf32(bv.w);
                *reinterpret_cast<uint4*>(&Bs[c * LDBr + kk]) = o4;
            }
        } else {
#pragma unroll
            for (int it = 0; it < (BN * BK) / 1024; it++) {
                int idx = (tid + it * 256) * 4;
                int c  = idx % BN;
                int kr = idx / BN;
                float4 bv = *reinterpret_cast<const float4*>(
                    &B[(long long)(k0 + kr) * ldb + colBase + c]);
                uint4 o4; o4.x = f2tf32(bv.x); o4.y = f2tf32(bv.y);
                o4.z = f2tf32(bv.z); o4.w = f2tf32(bv.w);
                *reinterpret_cast<uint4*>(&Bs[kr * LDBr + c]) = o4;
            }
        }
        __syncthreads();

#pragma unroll
        for (int ks = 0; ks < 4; ks++) {
            const int kk = ks * 8;
            uint32_t a[MI][4], b[NI][2];
#pragma unroll
            for (int mi = 0; mi < MI; mi++) {
                int r = warpM * (BM / 2) + mi * 16 + gid;
                a[mi][0] = As[r * LDAr + kk + tid4];
                a[mi][1] = As[(r + 8) * LDAr + kk + tid4];
                a[mi][2] = As[r * LDAr + kk + tid4 + 4];
                a[mi][3] = As[(r + 8) * LDAr + kk + tid4 + 4];
            }
#pragma unroll
            for (int ni = 0; ni < NI; ni++) {
                int col = warpN * (BN / 4) + ni * 8 + gid;
                if (TB) {
                    b[ni][0] = Bs[col * LDBr + kk + tid4];
                    b[ni][1] = Bs[col * LDBr + kk + tid4 + 4];
                } else {
                    b[ni][0] = Bs[(kk + tid4) * LDBr + col];
                    b[ni][1] = Bs[(kk + tid4 + 4) * LDBr + col];
                }
            }
#pragma unroll
            for (int mi = 0; mi < MI; mi++)
#pragma unroll
                for (int ni = 0; ni < NI; ni++) {
                    asm volatile(
                        "mma.sync.aligned.m16n8k8.row.col.f32.tf32.tf32.f32 "
                        "{%0,%1,%2,%3}, {%4,%5,%6,%7}, {%8,%9}, {%0,%1,%2,%3};"
                        : "+f"(acc[mi][ni][0]), "+f"(acc[mi][ni][1]),
                          "+f"(acc[mi][ni][2]), "+f"(acc[mi][ni][3])
                        : "r"(a[mi][0]), "r"(a[mi][1]), "r"(a[mi][2]), "r"(a[mi][3]),
                          "r"(b[ni][0]), "r"(b[ni][1]));
                }
        }
        __syncthreads();
    }

#pragma unroll
    for (int mi = 0; mi < MI; mi++) {
#pragma unroll
        for (int ni = 0; ni < NI; ni++) {
#pragma unroll
            for (int half = 0; half < 2; half++) {
                int row = rowBase + warpM * (BM / 2) + mi * 16 + gid + half * 8;
                int col = colBase + warpN * (BN / 4) + ni * 8 + tid4 * 2;
                float v0 = acc[mi][ni][half * 2 + 0];
                float v1 = acc[mi][ni][half * 2 + 1];
                long long ci = (long long)row * ldc + col;
                if (EPI == 0) {
                    C[ci]     = v0 + bias[col];
                    C[ci + 1] = v1 + bias[col + 1];
                } else if (EPI == 1) {
                    v0 += bias[col];
                    v1 += bias[col + 1];
                    C[ci]     = 0.5f * v0 * (1.0f + erff(v0 * 0.70710678118654752f));
                    C[ci + 1] = 0.5f * v1 * (1.0f + erff(v1 * 0.70710678118654752f));
                } else if (EPI == 2) {
                    C[ci]     += v0 + bias[col];
                    C[ci + 1] += v1 + bias[col + 1];
                } else {
                    C[ci]     = v0;
                    C[ci + 1] = v1;
                }
            }
        }
    }
}

// ---------------- launcher ----------------
extern "C" void kernel_launch(void* const* d_in, const int* in_sizes, int n_in,
                              void* d_out, int out_size)
{
    (void)n_in; (void)out_size;
    const float* x         = (const float*)d_in[0];
    const int*   ei        = (const int*)  d_in[1];
    const float* pos       = (const float*)d_in[3];
    const float* node_in_w = (const float*)d_in[4];
    const float* node_in_b = (const float*)d_in[5];
    const float* z_in      = (const float*)d_in[8];
    const float* z_out     = (const float*)d_in[9];
    const float* sp_mu     = (const float*)d_in[10];
    const float* sp_sigma  = (const float*)d_in[11];
    const float* sp_w      = (const float*)d_in[12];
    const float* sp_b      = (const float*)d_in[13];
    const float* Wq        = (const float*)d_in[14];
    const float* bq        = (const float*)d_in[15];
    const float* Wk        = (const float*)d_in[16];
    const float* bk        = (const float*)d_in[17];
    const float* Wv        = (const float*)d_in[18];
    const float* bv        = (const float*)d_in[19];
    const float* Wo        = (const float*)d_in[20];
    const float* bo        = (const float*)d_in[21];
    const float* ln1_g     = (const float*)d_in[22];
    const float* ln1_b     = (const float*)d_in[23];
    const float* ln2_g     = (const float*)d_in[24];
    const float* ln2_b     = (const float*)d_in[25];
    const float* ff1_w     = (const float*)d_in[26];
    const float* ff1_b     = (const float*)d_in[27];
    const float* ff2_w     = (const float*)d_in[28];
    const float* ff2_b     = (const float*)d_in[29];
    const float* out_w     = (const float*)d_in[30];
    const float* out_b     = (const float*)d_in[31];
    float* out = (float*)d_out;

    const int E = in_sizes[1] / 2;
    const float scale = 0.08838834764831845f;  // 1/sqrt(128)

    float *p_h, *p_xn, *p_bias, *p_q, *p_k, *p_v, *p_o, *p_ff;
    cudaGetSymbolAddress((void**)&p_h,    g_h);
    cudaGetSymbolAddress((void**)&p_xn,   g_xn);
    cudaGetSymbolAddress((void**)&p_bias, g_bias);
    cudaGetSymbolAddress((void**)&p_q,    g_q);
    cudaGetSymbolAddress((void**)&p_k,    g_k);
    cudaGetSymbolAddress((void**)&p_v,    g_v);
    cudaGetSymbolAddress((void**)&p_o,    g_o);
    cudaGetSymbolAddress((void**)&p_ff,   g_ff);

    // flash kernel dynamic smem: (2*128*132 + 128*136 + 1024) u32 = 208896 bytes
    const int FLASH_SMEM = (2 * 128 * 132 + 128 * 136 + 1024) * 4;
    cudaFuncSetAttribute(flash_kernel, cudaFuncAttributeMaxDynamicSharedMemorySize, FLASH_SMEM);

    deg_zero_kernel<<<(Nn + 255) / 256, 256>>>();
    deg_count_kernel<<<(E + 255) / 256, 256>>>(ei, E);
    embed_kernel<<<Nn, Dd>>>(x, node_in_w, node_in_b, z_in, z_out);
    spbias_kernel<<<(int)(((long long)Nn * Nn) / 256), 256>>>(pos, sp_mu, sp_sigma, sp_w, sp_b);

    const long long sHead = (long long)Nn * Dd;
    const long long sW    = (long long)Dd * Dd;

    for (int l = 0; l < Ll; l++) {
        ln_kernel<<<Nn, Dd>>>(p_h, p_xn, ln1_g + l * Dd, ln1_b + l * Dd);

        dim3 gQ(Dd / 128, Nn / 128, Hh);
        gemm_tf32<128, 128, false, 0><<<gQ, 256>>>(
            p_xn, Dd, 0, Wq + (long long)l * Hh * sW, Dd, sW,
            p_q, Dd, sHead, bq + (long long)l * Hh * Dd, Dd, Nn, Dd, Dd);
        gemm_tf32<128, 128, false, 0><<<gQ, 256>>>(
            p_xn, Dd, 0, Wk + (long long)l * Hh * sW, Dd, sW,
            p_k, Dd, sHead, bk + (long long)l * Hh * Dd, Dd, Nn, Dd, Dd);
        gemm_tf32<128, 128, false, 0><<<gQ, 256>>>(
            p_xn, Dd, 0, Wv + (long long)l * Hh * sW, Dd, sW,
            p_v, Dd, sHead, bv + (long long)l * Hh * Dd, Dd, Nn, Dd, Dd);

        // fused attention: scores + bias + softmax + attn.v
        flash_kernel<<<dim3(Nn / 128, Hh), 256, FLASH_SMEM>>>(
            p_q, p_k, p_v, p_bias, p_o, scale);

        // h += o @ Wo + bo
        dim3 gW2(Dd / 64, Nn / 64, 1);
        gemm_tf32<64, 64, false, 2><<<gW2, 256>>>(
            p_o, Hh * Dd, 0, Wo + (long long)l * Hh * Dd * Dd, Dd, 0,
            p_h, Dd, 0, bo + l * Dd, 0, Nn, Dd, Hh * Dd);

        ln_kernel<<<Nn, Dd>>>(p_h, p_xn, ln2_g + l * Dd, ln2_b + l * Dd);

        dim3 gF1(FFd / 128, Nn / 128, 1);
        gemm_tf32<128, 128, false, 1><<<gF1, 256>>>(
            p_xn, Dd, 0, ff1_w + (long long)l * Dd * FFd, FFd, 0,
            p_ff, FFd, 0, ff1_b + l * FFd, 0, Nn, FFd, Dd);

        dim3 gF2(Dd / 64, Nn / 64, 1);
        gemm_tf32<64, 64, false, 2><<<gF2, 256>>>(
            p_ff, FFd, 0, ff2_w + (long long)l * FFd * Dd, Dd, 0,
            p_h, Dd, 0, ff2_b + l * Dd, 0, Nn, Dd, FFd);
    }

    dim3 gO(OUTd / 64, Nn / 64, 1);
    gemm_tf32<64, 64, false, 0><<<gO, 256>>>(
        p_h, Dd, 0, out_w, OUTd, 0,
        out, OUTd, 0, out_b, 0, Nn, OUTd, Dd);
}

// round 6
// speedup vs baseline: 3.0789x; 1.0625x over previous
#include <cuda_runtime.h>
#include <math.h>
#include <stdint.h>

// ---------------- problem constants ----------------
#define Nn   2048
#define Dd   128
#define Hh   8
#define FFd  512
#define OUTd 64
#define Ll   3
#define HSd  8
#define DEGMAX 64
#define LOG2E 1.4426950408889634f

// ---------------- device scratch (no allocations allowed) ----------------
__device__ float g_h[Nn * Dd];
__device__ float g_xn[Nn * Dd];
__device__ float g_bias[(size_t)Nn * Nn];
__device__ float g_q[Hh * Nn * Dd];
__device__ float g_k[Hh * Nn * Dd];
__device__ float g_v[Hh * Nn * Dd];
__device__ float g_o[Nn * Hh * Dd];
__device__ float g_ff[Nn * FFd];
__device__ int   g_indeg[Nn];
__device__ int   g_outdeg[Nn];

// ---------------- helpers ----------------
__device__ __forceinline__ uint32_t f2tf32(float f) {
    uint32_t r;
    asm("cvt.rna.tf32.f32 %0, %1;" : "=r"(r) : "f"(f));
    return r;
}

__device__ __forceinline__ void cpasync16(uint32_t dst, const void* src) {
    asm volatile("cp.async.cg.shared.global [%0], [%1], 16;" :: "r"(dst), "l"(src));
}
#define CP_COMMIT() asm volatile("cp.async.commit_group;")
#define CP_WAIT0()  asm volatile("cp.async.wait_group 0;")
#define CP_WAIT1()  asm volatile("cp.async.wait_group 1;")

// ---------------- small kernels ----------------
__global__ void deg_zero_kernel() {
    int i = blockIdx.x * blockDim.x + threadIdx.x;
    if (i < Nn) { g_indeg[i] = 0; g_outdeg[i] = 0; }
}

__global__ void deg_count_kernel(const int* __restrict__ ei, int E) {
    int e = blockIdx.x * blockDim.x + threadIdx.x;
    if (e < E) {
        atomicAdd(&g_outdeg[ei[e]], 1);
        atomicAdd(&g_indeg[ei[E + e]], 1);
    }
}

__global__ void embed_kernel(const float* __restrict__ x, const float* __restrict__ W,
                             const float* __restrict__ b, const float* __restrict__ z_in,
                             const float* __restrict__ z_out) {
    int n = blockIdx.x, d = threadIdx.x;
    float acc = b[d];
#pragma unroll
    for (int i = 0; i < 16; i++) acc = fmaf(x[n * 16 + i], W[i * Dd + d], acc);
    int di = min(g_indeg[n],  DEGMAX - 1);
    int dn = min(g_outdeg[n], DEGMAX - 1);
    g_h[n * Dd + d] = acc + z_in[di * Dd + d] + z_out[dn * Dd + d];
}

// triangular spatial bias: one block per (bi<=bj) 32x32 tile pair.
// Writes bias * LOG2E (consumed only by flash exp2-domain softmax).
__global__ void __launch_bounds__(256) spbias_tri_kernel(
    const float* __restrict__ pos, const float* __restrict__ mu,
    const float* __restrict__ sigma, const float* __restrict__ w,
    const float* __restrict__ b0)
{
    const int NT = Nn / 32;          // 64
    int p = blockIdx.x;
    float fp = (float)p;
    int twoN1 = 2 * NT + 1;
    int bi = (int)((twoN1 - sqrtf((float)twoN1 * twoN1 - 8.0f * fp)) * 0.5f);
    if (bi < 0) bi = 0;
    if (bi > NT - 1) bi = NT - 1;
    while (bi + 1 <= NT - 1 && (bi + 1) * NT - (bi + 1) * bi / 2 <= p) bi++;
    while (bi * NT - bi * (bi - 1) / 2 > p) bi--;
    int bj = bi + (p - (bi * NT - bi * (bi - 1) / 2));

    __shared__ float st[32][33];
    int tid = threadIdx.x;
    int r  = tid >> 3;
    int c0 = (tid & 7) << 2;

    int i = bi * 32 + r;
    float pix = pos[i * 3 + 0], piy = pos[i * 3 + 1], piz = pos[i * 3 + 2];
    float val[4];
#pragma unroll
    for (int k = 0; k < 4; k++) {
        int j = bj * 32 + c0 + k;
        float dx = pix - pos[j * 3 + 0];
        float dy = piy - pos[j * 3 + 1];
        float dz = piz - pos[j * 3 + 2];
        float d = sqrtf(dx * dx + dy * dy + dz * dz + 1e-12f);
        float acc = b0[0];
#pragma unroll
        for (int t = 0; t < HSd; t++) {
            float u = (d - mu[t]) / sigma[t];
            acc = fmaf(__expf(-0.5f * u * u), w[t], acc);
        }
        val[k] = acc * LOG2E;
        st[r][c0 + k] = val[k];
    }
    float4 o4 = make_float4(val[0], val[1], val[2], val[3]);
    *reinterpret_cast<float4*>(&g_bias[(long long)i * Nn + bj * 32 + c0]) = o4;
    __syncthreads();
    if (bi != bj) {
        float4 t4;
        t4.x = st[c0 + 0][r];
        t4.y = st[c0 + 1][r];
        t4.z = st[c0 + 2][r];
        t4.w = st[c0 + 3][r];
        *reinterpret_cast<float4*>(&g_bias[(long long)(bj * 32 + r) * Nn + bi * 32 + c0]) = t4;
    }
}

__global__ void ln_kernel(const float* __restrict__ x, float* __restrict__ y,
                          const float* __restrict__ g, const float* __restrict__ b) {
    int n = blockIdx.x, t = threadIdx.x;
    float v = x[n * Dd + t];
    float s = v, sq = v * v;
#pragma unroll
    for (int o = 16; o > 0; o >>= 1) {
        s  += __shfl_xor_sync(0xffffffffu, s,  o);
        sq += __shfl_xor_sync(0xffffffffu, sq, o);
    }
    __shared__ float ss[4], ssq[4];
    if ((t & 31) == 0) { ss[t >> 5] = s; ssq[t >> 5] = sq; }
    __syncthreads();
    float S = ss[0] + ss[1] + ss[2] + ss[3];
    float Q = ssq[0] + ssq[1] + ssq[2] + ssq[3];
    float mean = S * (1.0f / Dd);
    float var  = Q * (1.0f / Dd) - mean * mean;
    y[n * Dd + t] = (v - mean) * rsqrtf(var + 1e-5f) * g[t] + b[t];
}

// ---------------- fused flash attention (tf32 mma, cp.async pipelined) ----------------
// Q/K/V inputs are already tf32-rounded floats (written by QKV gemm EPI 5).
// Bias is pre-multiplied by LOG2E; scale2 = scale * LOG2E; softmax in exp2 domain.
__global__ void __launch_bounds__(256, 1)
flash_kernel(const float* __restrict__ Qg, const float* __restrict__ Kg,
             const float* __restrict__ Vg, const float* __restrict__ Bias,
             float* __restrict__ Og, float scale2)
{
    extern __shared__ uint32_t sh[];
    uint32_t* Qs = sh;                       // 128*132
    uint32_t* Ps = sh + 128 * 132;           // 128*132 (K, later P)
    uint32_t* Vs = sh + 2 * 128 * 132;       // 128*136
    float* redM = (float*)(sh + 2 * 128 * 132 + 128 * 136);   // [128][4]
    float* redS = redM + 512;                                  // [128][4]

    const int tid  = threadIdx.x;
    const int wid  = tid >> 5, lane = tid & 31;
    const int gid  = lane >> 2, tid4 = lane & 3;
    const int warpM = wid & 1, warpN = wid >> 1;
    const int qBase = blockIdx.x * 128;
    const int head  = blockIdx.y;
    const int r0 = warpM * 64;
    const int c0 = warpN * 32;

    const float* Qh = Qg + (long long)head * Nn * Dd;
    const float* Kh = Kg + (long long)head * Nn * Dd;
    const float* Vh = Vg + (long long)head * Nn * Dd;

    const uint32_t qsb = (uint32_t)__cvta_generic_to_shared(Qs);
    const uint32_t psb = (uint32_t)__cvta_generic_to_shared(Ps);
    const uint32_t vsb = (uint32_t)__cvta_generic_to_shared(Vs);

    // stage Q tile via cp.async (group 0)
#pragma unroll
    for (int it = 0; it < 16; it++) {
        int idx = (tid + it * 256) * 4;
        int r = idx >> 7, kk = idx & 127;
        cpasync16(qsb + (r * 132 + kk) * 4, &Qh[(long long)(qBase + r) * Dd + kk]);
    }
    CP_COMMIT();

    float accO[4][4][4];
#pragma unroll
    for (int mi = 0; mi < 4; mi++)
#pragma unroll
        for (int ni = 0; ni < 4; ni++)
#pragma unroll
            for (int r = 0; r < 4; r++) accO[mi][ni][r] = 0.f;
    float mrow[4][2], lrow[4][2];
#pragma unroll
    for (int mi = 0; mi < 4; mi++) {
        mrow[mi][0] = -1e30f; mrow[mi][1] = -1e30f;
        lrow[mi][0] = 0.f;    lrow[mi][1] = 0.f;
    }

    for (int j = 0; j < 16; j++) {
        const int kBase = j * 128;
        // stage K tile (own group) — needed at S-mma
#pragma unroll
        for (int it = 0; it < 16; it++) {
            int idx = (tid + it * 256) * 4;
            int c = idx >> 7, kk = idx & 127;
            cpasync16(psb + (c * 132 + kk) * 4, &Kh[(long long)(kBase + c) * Dd + kk]);
        }
        CP_COMMIT();
        // stage V tile (own group) — needed only at PV-mma; stays in flight
#pragma unroll
        for (int it = 0; it < 16; it++) {
            int idx = (tid + it * 256) * 4;
            int kr = idx >> 7, c = idx & 127;
            cpasync16(vsb + (kr * 136 + c) * 4, &Vh[(long long)(kBase + kr) * Dd + c]);
        }
        CP_COMMIT();
        CP_WAIT1();            // Q(+iter0) and K arrived; V may be outstanding
        __syncthreads();

        // bias burst (MLP 32, overlaps S-mma scheduling)
        float2 bl[4][2][4];
#pragma unroll
        for (int mi = 0; mi < 4; mi++)
#pragma unroll
            for (int half = 0; half < 2; half++) {
                int rl = r0 + mi * 16 + gid + half * 8;
                long long brow = (long long)(qBase + rl) * Nn + kBase;
#pragma unroll
                for (int ni = 0; ni < 4; ni++)
                    bl[mi][half][ni] = *reinterpret_cast<const float2*>(
                        &Bias[brow + c0 + ni * 8 + tid4 * 2]);
            }

        // ---- S = Q . K^T ----
        float accS[4][4][4];
#pragma unroll
        for (int mi = 0; mi < 4; mi++)
#pragma unroll
            for (int ni = 0; ni < 4; ni++)
#pragma unroll
                for (int r = 0; r < 4; r++) accS[mi][ni][r] = 0.f;
#pragma unroll
        for (int ks = 0; ks < 16; ks++) {
            const int kk = ks * 8;
            uint32_t a[4][4], b[4][2];
#pragma unroll
            for (int mi = 0; mi < 4; mi++) {
                int r = r0 + mi * 16 + gid;
                a[mi][0] = Qs[r * 132 + kk + tid4];
                a[mi][1] = Qs[(r + 8) * 132 + kk + tid4];
                a[mi][2] = Qs[r * 132 + kk + tid4 + 4];
                a[mi][3] = Qs[(r + 8) * 132 + kk + tid4 + 4];
            }
#pragma unroll
            for (int ni = 0; ni < 4; ni++) {
                int col = c0 + ni * 8 + gid;
                b[ni][0] = Ps[col * 132 + kk + tid4];
                b[ni][1] = Ps[col * 132 + kk + tid4 + 4];
            }
#pragma unroll
            for (int mi = 0; mi < 4; mi++)
#pragma unroll
                for (int ni = 0; ni < 4; ni++) {
                    asm volatile(
                        "mma.sync.aligned.m16n8k8.row.col.f32.tf32.tf32.f32 "
                        "{%0,%1,%2,%3}, {%4,%5,%6,%7}, {%8,%9}, {%0,%1,%2,%3};"
                        : "+f"(accS[mi][ni][0]), "+f"(accS[mi][ni][1]),
                          "+f"(accS[mi][ni][2]), "+f"(accS[mi][ni][3])
                        : "r"(a[mi][0]), "r"(a[mi][1]), "r"(a[mi][2]), "r"(a[mi][3]),
                          "r"(b[ni][0]), "r"(b[ni][1]));
                }
        }
        __syncthreads();   // all warps done reading K before P overwrites Ps

        // ---- scale + bias (exp2 domain), per-warp row-max partials ----
#pragma unroll
        for (int mi = 0; mi < 4; mi++) {
#pragma unroll
            for (int half = 0; half < 2; half++) {
                int rl = r0 + mi * 16 + gid + half * 8;
                float rmax = -1e30f;
#pragma unroll
                for (int ni = 0; ni < 4; ni++) {
                    float2 bb = bl[mi][half][ni];
                    float s0 = fmaf(accS[mi][ni][half * 2 + 0], scale2, bb.x);
                    float s1 = fmaf(accS[mi][ni][half * 2 + 1], scale2, bb.y);
                    accS[mi][ni][half * 2 + 0] = s0;
                    accS[mi][ni][half * 2 + 1] = s1;
                    rmax = fmaxf(rmax, fmaxf(s0, s1));
                }
                rmax = fmaxf(rmax, __shfl_xor_sync(0xffffffffu, rmax, 1));
                rmax = fmaxf(rmax, __shfl_xor_sync(0xffffffffu, rmax, 2));
                if (tid4 == 0) redM[rl * 4 + warpN] = rmax;
            }
        }
        __syncthreads();

        // ---- m/l update, p = exp2, rescale O, write P ----
#pragma unroll
        for (int mi = 0; mi < 4; mi++) {
#pragma unroll
            for (int half = 0; half < 2; half++) {
                int rl = r0 + mi * 16 + gid + half * 8;
                float tm = fmaxf(fmaxf(redM[rl * 4 + 0], redM[rl * 4 + 1]),
                                 fmaxf(redM[rl * 4 + 2], redM[rl * 4 + 3]));
                float mold = mrow[mi][half];
                float mnew = fmaxf(mold, tm);
                float fac  = exp2f(mold - mnew);
                mrow[mi][half] = mnew;
                lrow[mi][half] *= fac;
                float psum = 0.f;
#pragma unroll
                for (int ni = 0; ni < 4; ni++) {
                    float p0 = exp2f(accS[mi][ni][half * 2 + 0] - mnew);
                    float p1 = exp2f(accS[mi][ni][half * 2 + 1] - mnew);
                    accS[mi][ni][half * 2 + 0] = p0;
                    accS[mi][ni][half * 2 + 1] = p1;
                    psum += p0 + p1;
                    accO[mi][ni][half * 2 + 0] *= fac;
                    accO[mi][ni][half * 2 + 1] *= fac;
                }
                psum += __shfl_xor_sync(0xffffffffu, psum, 1);
                psum += __shfl_xor_sync(0xffffffffu, psum, 2);
                if (tid4 == 0) redS[rl * 4 + warpN] = psum;
            }
        }
        // write P (row-major [q][key]) into Ps
#pragma unroll
        for (int mi = 0; mi < 4; mi++)
#pragma unroll
            for (int half = 0; half < 2; half++) {
                int rl = r0 + mi * 16 + gid + half * 8;
#pragma unroll
                for (int ni = 0; ni < 4; ni++) {
                    int cl = c0 + ni * 8 + tid4 * 2;
                    Ps[rl * 132 + cl]     = f2tf32(accS[mi][ni][half * 2 + 0]);
                    Ps[rl * 132 + cl + 1] = f2tf32(accS[mi][ni][half * 2 + 1]);
                }
            }
        CP_WAIT0();            // V arrived (hidden behind S-mma + softmax)
        __syncthreads();

        // accumulate tile row-sums into l
#pragma unroll
        for (int mi = 0; mi < 4; mi++)
#pragma unroll
            for (int half = 0; half < 2; half++) {
                int rl = r0 + mi * 16 + gid + half * 8;
                lrow[mi][half] += redS[rl * 4 + 0] + redS[rl * 4 + 1]
                                + redS[rl * 4 + 2] + redS[rl * 4 + 3];
            }

        // ---- O += P . V ----
#pragma unroll
        for (int ks = 0; ks < 16; ks++) {
            const int kk = ks * 8;
            uint32_t a[4][4], b[4][2];
#pragma unroll
            for (int mi = 0; mi < 4; mi++) {
                int r = r0 + mi * 16 + gid;
                a[mi][0] = Ps[r * 132 + kk + tid4];
                a[mi][1] = Ps[(r + 8) * 132 + kk + tid4];
                a[mi][2] = Ps[r * 132 + kk + tid4 + 4];
                a[mi][3] = Ps[(r + 8) * 132 + kk + tid4 + 4];
            }
#pragma unroll
            for (int ni = 0; ni < 4; ni++) {
                int col = c0 + ni * 8 + gid;
                b[ni][0] = Vs[(kk + tid4) * 136 + col];
                b[ni][1] = Vs[(kk + tid4 + 4) * 136 + col];
            }
#pragma unroll
            for (int mi = 0; mi < 4; mi++)
#pragma unroll
                for (int ni = 0; ni < 4; ni++) {
                    asm volatile(
                        "mma.sync.aligned.m16n8k8.row.col.f32.tf32.tf32.f32 "
                        "{%0,%1,%2,%3}, {%4,%5,%6,%7}, {%8,%9}, {%0,%1,%2,%3};"
                        : "+f"(accO[mi][ni][0]), "+f"(accO[mi][ni][1]),
                          "+f"(accO[mi][ni][2]), "+f"(accO[mi][ni][3])
                        : "r"(a[mi][0]), "r"(a[mi][1]), "r"(a[mi][2]), "r"(a[mi][3]),
                          "r"(b[ni][0]), "r"(b[ni][1]));
                }
        }
        __syncthreads();   // before next iteration restages Ps/Vs
    }

    // ---- epilogue: O / l -> g_o[q][head*128+d] ----
#pragma unroll
    for (int mi = 0; mi < 4; mi++)
#pragma unroll
        for (int half = 0; half < 2; half++) {
            int rl = r0 + mi * 16 + gid + half * 8;
            float inv = 1.0f / lrow[mi][half];
#pragma unroll
            for (int ni = 0; ni < 4; ni++) {
                int cl = c0 + ni * 8 + tid4 * 2;
                float2 ov;
                ov.x = accO[mi][ni][half * 2 + 0] * inv;
                ov.y = accO[mi][ni][half * 2 + 1] * inv;
                *reinterpret_cast<float2*>(
                    &Og[(long long)(qBase + rl) * (Hh * Dd) + head * Dd + cl]) = ov;
            }
        }
}

// ---------------- tf32 tensor-core GEMM ----------------
// EPI: 0=+bias[col]  1=gelu(+bias[col])  2=C+=acc+bias[col]  4=plain
//      5=+bias[col], stored pre-rounded to tf32 bit pattern
template <int BM, int BN, bool TB, int EPI>
__global__ void __launch_bounds__(256, 2)
gemm_tf32(const float* __restrict__ A, int lda, long long sA,
          const float* __restrict__ B, int ldb, long long sB,
          float* __restrict__ C, int ldc, long long sC,
          const float* __restrict__ bias, int sBias,
          int M, int Nc, int K)
{
    constexpr int BK   = 32;
    constexpr int LDAr = BK + 4;
    constexpr int LDBr = TB ? (BK + 4) : (BN + 8);
    constexpr int BSZ  = TB ? BN * LDBr : BK * LDBr;
    constexpr int MI   = BM / 32;
    constexpr int NI   = BN / 32;

    const int z = blockIdx.z;
    A += (long long)z * sA;
    B += (long long)z * sB;
    C += (long long)z * sC;
    if (EPI == 0 || EPI == 1 || EPI == 2 || EPI == 5) bias += (long long)z * sBias;

    __shared__ uint32_t As[BM * LDAr];
    __shared__ uint32_t Bs[BSZ];

    const int tid  = threadIdx.x;
    const int wid  = tid >> 5;
    const int lane = tid & 31;
    const int gid  = lane >> 2;
    const int tid4 = lane & 3;
    const int warpM = wid & 1;
    const int warpN = wid >> 1;
    const int rowBase = blockIdx.y * BM;
    const int colBase = blockIdx.x * BN;

    float acc[MI][NI][4];
#pragma unroll
    for (int mi = 0; mi < MI; mi++)
#pragma unroll
        for (int ni = 0; ni < NI; ni++)
#pragma unroll
            for (int r = 0; r < 4; r++) acc[mi][ni][r] = 0.f;

    for (int k0 = 0; k0 < K; k0 += BK) {
#pragma unroll
        for (int it = 0; it < (BM * BK) / 1024; it++) {
            int idx = (tid + it * 256) * 4;
            int r  = idx / BK;
            int kk = idx % BK;
            float4 av = *reinterpret_cast<const float4*>(
                &A[(long long)(rowBase + r) * lda + k0 + kk]);
            uint4 o4; o4.x = f2tf32(av.x); o4.y = f2tf32(av.y);
            o4.z = f2tf32(av.z); o4.w = f2tf32(av.w);
            *reinterpret_cast<uint4*>(&As[r * LDAr + kk]) = o4;
        }
        if (TB) {
#pragma unroll
            for (int it = 0; it < (BN * BK) / 1024; it++) {
                int idx = (tid + it * 256) * 4;
                int c  = idx / BK;
                int kk = idx % BK;
                float4 bv = *reinterpret_cast<const float4*>(
                    &B[(long long)(colBase + c) * ldb + k0 + kk]);
                uint4 o4; o4.x = f2tf32(bv.x); o4.y = f2tf32(bv.y);
                o4.z = f2tf32(bv.z); o4.w = f2tf32(bv.w);
                *reinterpret_cast<uint4*>(&Bs[c * LDBr + kk]) = o4;
            }
        } else {
#pragma unroll
            for (int it = 0; it < (BN * BK) / 1024; it++) {
                int idx = (tid + it * 256) * 4;
                int c  = idx % BN;
                int kr = idx / BN;
                float4 bv = *reinterpret_cast<const float4*>(
                    &B[(long long)(k0 + kr) * ldb + colBase + c]);
                uint4 o4; o4.x = f2tf32(bv.x); o4.y = f2tf32(bv.y);
                o4.z = f2tf32(bv.z); o4.w = f2tf32(bv.w);
                *reinterpret_cast<uint4*>(&Bs[kr * LDBr + c]) = o4;
            }
        }
        __syncthreads();

#pragma unroll
        for (int ks = 0; ks < 4; ks++) {
            const int kk = ks * 8;
            uint32_t a[MI][4], b[NI][2];
#pragma unroll
            for (int mi = 0; mi < MI; mi++) {
                int r = warpM * (BM / 2) + mi * 16 + gid;
                a[mi][0] = As[r * LDAr + kk + tid4];
                a[mi][1] = As[(r + 8) * LDAr + kk + tid4];
                a[mi][2] = As[r * LDAr + kk + tid4 + 4];
                a[mi][3] = As[(r + 8) * LDAr + kk + tid4 + 4];
            }
#pragma unroll
            for (int ni = 0; ni < NI; ni++) {
                int col = warpN * (BN / 4) + ni * 8 + gid;
                if (TB) {
                    b[ni][0] = Bs[col * LDBr + kk + tid4];
                    b[ni][1] = Bs[col * LDBr + kk + tid4 + 4];
                } else {
                    b[ni][0] = Bs[(kk + tid4) * LDBr + col];
                    b[ni][1] = Bs[(kk + tid4 + 4) * LDBr + col];
                }
            }
#pragma unroll
            for (int mi = 0; mi < MI; mi++)
#pragma unroll
                for (int ni = 0; ni < NI; ni++) {
                    asm volatile(
                        "mma.sync.aligned.m16n8k8.row.col.f32.tf32.tf32.f32 "
                        "{%0,%1,%2,%3}, {%4,%5,%6,%7}, {%8,%9}, {%0,%1,%2,%3};"
                        : "+f"(acc[mi][ni][0]), "+f"(acc[mi][ni][1]),
                          "+f"(acc[mi][ni][2]), "+f"(acc[mi][ni][3])
                        : "r"(a[mi][0]), "r"(a[mi][1]), "r"(a[mi][2]), "r"(a[mi][3]),
                          "r"(b[ni][0]), "r"(b[ni][1]));
                }
        }
        __syncthreads();
    }

#pragma unroll
    for (int mi = 0; mi < MI; mi++) {
#pragma unroll
        for (int ni = 0; ni < NI; ni++) {
#pragma unroll
            for (int half = 0; half < 2; half++) {
                int row = rowBase + warpM * (BM / 2) + mi * 16 + gid + half * 8;
                int col = colBase + warpN * (BN / 4) + ni * 8 + tid4 * 2;
                float v0 = acc[mi][ni][half * 2 + 0];
                float v1 = acc[mi][ni][half * 2 + 1];
                long long ci = (long long)row * ldc + col;
                if (EPI == 0) {
                    C[ci]     = v0 + bias[col];
                    C[ci + 1] = v1 + bias[col + 1];
                } else if (EPI == 1) {
                    v0 += bias[col];
                    v1 += bias[col + 1];
                    C[ci]     = 0.5f * v0 * (1.0f + erff(v0 * 0.70710678118654752f));
                    C[ci + 1] = 0.5f * v1 * (1.0f + erff(v1 * 0.70710678118654752f));
                } else if (EPI == 2) {
                    C[ci]     += v0 + bias[col];
                    C[ci + 1] += v1 + bias[col + 1];
                } else if (EPI == 5) {
                    C[ci]     = __uint_as_float(f2tf32(v0 + bias[col]));
                    C[ci + 1] = __uint_as_float(f2tf32(v1 + bias[col + 1]));
                } else {
                    C[ci]     = v0;
                    C[ci + 1] = v1;
                }
            }
        }
    }
}

// ---------------- launcher ----------------
extern "C" void kernel_launch(void* const* d_in, const int* in_sizes, int n_in,
                              void* d_out, int out_size)
{
    (void)n_in; (void)out_size;
    const float* x         = (const float*)d_in[0];
    const int*   ei        = (const int*)  d_in[1];
    const float* pos       = (const float*)d_in[3];
    const float* node_in_w = (const float*)d_in[4];
    const float* node_in_b = (const float*)d_in[5];
    const float* z_in      = (const float*)d_in[8];
    const float* z_out     = (const float*)d_in[9];
    const float* sp_mu     = (const float*)d_in[10];
    const float* sp_sigma  = (const float*)d_in[11];
    const float* sp_w      = (const float*)d_in[12];
    const float* sp_b      = (const float*)d_in[13];
    const float* Wq        = (const float*)d_in[14];
    const float* bq        = (const float*)d_in[15];
    const float* Wk        = (const float*)d_in[16];
    const float* bk        = (const float*)d_in[17];
    const float* Wv        = (const float*)d_in[18];
    const float* bv        = (const float*)d_in[19];
    const float* Wo        = (const float*)d_in[20];
    const float* bo        = (const float*)d_in[21];
    const float* ln1_g     = (const float*)d_in[22];
    const float* ln1_b     = (const float*)d_in[23];
    const float* ln2_g     = (const float*)d_in[24];
    const float* ln2_b     = (const float*)d_in[25];
    const float* ff1_w     = (const float*)d_in[26];
    const float* ff1_b     = (const float*)d_in[27];
    const float* ff2_w     = (const float*)d_in[28];
    const float* ff2_b     = (const float*)d_in[29];
    const float* out_w     = (const float*)d_in[30];
    const float* out_b     = (const float*)d_in[31];
    float* out = (float*)d_out;

    const int E = in_sizes[1] / 2;
    const float scale2 = 0.08838834764831845f * LOG2E;

    float *p_h, *p_xn, *p_bias, *p_q, *p_k, *p_v, *p_o, *p_ff;
    cudaGetSymbolAddress((void**)&p_h,    g_h);
    cudaGetSymbolAddress((void**)&p_xn,   g_xn);
    cudaGetSymbolAddress((void**)&p_bias, g_bias);
    cudaGetSymbolAddress((void**)&p_q,    g_q);
    cudaGetSymbolAddress((void**)&p_k,    g_k);
    cudaGetSymbolAddress((void**)&p_v,    g_v);
    cudaGetSymbolAddress((void**)&p_o,    g_o);
    cudaGetSymbolAddress((void**)&p_ff,   g_ff);

    const int FLASH_SMEM = (2 * 128 * 132 + 128 * 136 + 1024) * 4;
    cudaFuncSetAttribute(flash_kernel, cudaFuncAttributeMaxDynamicSharedMemorySize, FLASH_SMEM);

    deg_zero_kernel<<<(Nn + 255) / 256, 256>>>();
    deg_count_kernel<<<(E + 255) / 256, 256>>>(ei, E);
    embed_kernel<<<Nn, Dd>>>(x, node_in_w, node_in_b, z_in, z_out);
    {
        const int NT = Nn / 32;
        spbias_tri_kernel<<<NT * (NT + 1) / 2, 256>>>(pos, sp_mu, sp_sigma, sp_w, sp_b);
    }

    const long long sHead = (long long)Nn * Dd;
    const long long sW    = (long long)Dd * Dd;

    for (int l = 0; l < Ll; l++) {
        ln_kernel<<<Nn, Dd>>>(p_h, p_xn, ln1_g + l * Dd, ln1_b + l * Dd);

        // QKV projections: outputs pre-rounded to tf32 (EPI 5)
        dim3 gQ(Dd / 128, Nn / 128, Hh);
        gemm_tf32<128, 128, false, 5><<<gQ, 256>>>(
            p_xn, Dd, 0, Wq + (long long)l * Hh * sW, Dd, sW,
            p_q, Dd, sHead, bq + (long long)l * Hh * Dd, Dd, Nn, Dd, Dd);
        gemm_tf32<128, 128, false, 5><<<gQ, 256>>>(
            p_xn, Dd, 0, Wk + (long long)l * Hh * sW, Dd, sW,
            p_k, Dd, sHead, bk + (long long)l * Hh * Dd, Dd, Nn, Dd, Dd);
        gemm_tf32<128, 128, false, 5><<<gQ, 256>>>(
            p_xn, Dd, 0, Wv + (long long)l * Hh * sW, Dd, sW,
            p_v, Dd, sHead, bv + (long long)l * Hh * Dd, Dd, Nn, Dd, Dd);

        // fused attention: scores + bias + softmax + attn.v (exp2 domain)
        flash_kernel<<<dim3(Nn / 128, Hh), 256, FLASH_SMEM>>>(
            p_q, p_k, p_v, p_bias, p_o, scale2);

        // h += o @ Wo + bo
        dim3 gW2(Dd / 64, Nn / 64, 1);
        gemm_tf32<64, 64, false, 2><<<gW2, 256>>>(
            p_o, Hh * Dd, 0, Wo + (long long)l * Hh * Dd * Dd, Dd, 0,
            p_h, Dd, 0, bo + l * Dd, 0, Nn, Dd, Hh * Dd);

        ln_kernel<<<Nn, Dd>>>(p_h, p_xn, ln2_g + l * Dd, ln2_b + l * Dd);

        dim3 gF1(FFd / 128, Nn / 128, 1);
        gemm_tf32<128, 128, false, 1><<<gF1, 256>>>(
            p_xn, Dd, 0, ff1_w + (long long)l * Dd * FFd, FFd, 0,
            p_ff, FFd, 0, ff1_b + l * FFd, 0, Nn, FFd, Dd);

        dim3 gF2(Dd / 64, Nn / 64, 1);
        gemm_tf32<64, 64, false, 2><<<gF2, 256>>>(
            p_ff, FFd, 0, ff2_w + (long long)l * FFd * Dd, Dd, 0,
            p_h, Dd, 0, ff2_b + l * Dd, 0, Nn, Dd, FFd);
    }

    dim3 gO(OUTd / 64, Nn / 64, 1);
    gemm_tf32<64, 64, false, 0><<<gO, 256>>>(
        p_h, Dd, 0, out_w, OUTd, 0,
        out, OUTd, 0, out_b, 0, Nn, OUTd, Dd);
}

// round 8
// speedup vs baseline: 3.4778x; 1.1296x over previous
#include <cuda_runtime.h>
#include <math.h>
#include <stdint.h>

// ---------------- problem constants ----------------
#define Nn   2048
#define Dd   128
#define Hh   8
#define FFd  512
#define OUTd 64
#define Ll   3
#define HSd  8
#define DEGMAX 64
#define LOG2E 1.4426950408889634f

// ---------------- device scratch (no allocations allowed) ----------------
__device__ float g_h[Nn * Dd];
__device__ float g_xn[Nn * Dd];
__device__ float g_bias[(size_t)Nn * Nn];
__device__ float g_qkv[3 * Hh * Nn * Dd];           // [m][h][n][d], tf32-rounded
__device__ float g_o[Nn * Hh * Dd];                  // tf32-rounded
__device__ float g_ff[Nn * FFd];                     // tf32-rounded
__device__ float g_wqkv[Ll * 3 * Hh * Dd * Dd];      // rounded weights
__device__ float g_bqkv[Ll * 3 * Hh * Dd];
__device__ float g_wo[Ll * Hh * Dd * Dd];
__device__ float g_wff1[Ll * Dd * FFd];
__device__ float g_wff2[Ll * FFd * Dd];
__device__ int   g_indeg[Nn];
__device__ int   g_outdeg[Nn];

// ---------------- helpers ----------------
__device__ __forceinline__ uint32_t f2tf32(float f) {
    uint32_t r;
    asm("cvt.rna.tf32.f32 %0, %1;" : "=r"(r) : "f"(f));
    return r;
}
__device__ __forceinline__ float roundtf(float f) { return __uint_as_float(f2tf32(f)); }

__device__ __forceinline__ void cpasync16(uint32_t dst, const void* src) {
    asm volatile("cp.async.cg.shared.global [%0], [%1], 16;" :: "r"(dst), "l"(src));
}
#define CP_COMMIT() asm volatile("cp.async.commit_group;")
#define CP_WAIT0()  asm volatile("cp.async.wait_group 0;")
#define CP_WAIT1()  asm volatile("cp.async.wait_group 1;")

// ---------------- prep kernels (round weights once) ----------------
__global__ void prep_qkv_w(const float* __restrict__ Wq, const float* __restrict__ Wk,
                           const float* __restrict__ Wv) {
    long long i = (long long)blockIdx.x * blockDim.x + threadIdx.x;
    const long long per = (long long)Hh * Dd * Dd;             // 131072
    const long long tot = (long long)Ll * 3 * per;
    if (i >= tot) return;
    int l = (int)(i / (3 * per));
    long long rem = i % (3 * per);
    int m = (int)(rem / per);
    long long off = rem % per;
    const float* src = (m == 0) ? Wq : (m == 1) ? Wk : Wv;
    g_wqkv[i] = roundtf(src[(long long)l * per + off]);
}

__global__ void prep_qkv_b(const float* __restrict__ bq, const float* __restrict__ bk,
                           const float* __restrict__ bv) {
    int i = blockIdx.x * blockDim.x + threadIdx.x;
    const int per = Hh * Dd;                                    // 1024
    const int tot = Ll * 3 * per;
    if (i >= tot) return;
    int l = i / (3 * per);
    int rem = i % (3 * per);
    int m = rem / per;
    int off = rem % per;
    const float* src = (m == 0) ? bq : (m == 1) ? bk : bv;
    g_bqkv[i] = src[l * per + off];
}

__global__ void prep_round(const float* __restrict__ src, float* __restrict__ dst, int n) {
    int i = blockIdx.x * blockDim.x + threadIdx.x;
    if (i < n) dst[i] = roundtf(src[i]);
}

// ---------------- small kernels ----------------
__global__ void deg_zero_kernel() {
    int i = blockIdx.x * blockDim.x + threadIdx.x;
    if (i < Nn) { g_indeg[i] = 0; g_outdeg[i] = 0; }
}

__global__ void deg_count_kernel(const int* __restrict__ ei, int E) {
    int e = blockIdx.x * blockDim.x + threadIdx.x;
    if (e < E) {
        atomicAdd(&g_outdeg[ei[e]], 1);
        atomicAdd(&g_indeg[ei[E + e]], 1);
    }
}

__global__ void embed_kernel(const float* __restrict__ x, const float* __restrict__ W,
                             const float* __restrict__ b, const float* __restrict__ z_in,
                             const float* __restrict__ z_out) {
    int n = blockIdx.x, d = threadIdx.x;
    float acc = b[d];
#pragma unroll
    for (int i = 0; i < 16; i++) acc = fmaf(x[n * 16 + i], W[i * Dd + d], acc);
    int di = min(g_indeg[n],  DEGMAX - 1);
    int dn = min(g_outdeg[n], DEGMAX - 1);
    g_h[n * Dd + d] = acc + z_in[di * Dd + d] + z_out[dn * Dd + d];
}

// triangular spatial bias (writes bias * LOG2E)
__global__ void __launch_bounds__(256) spbias_tri_kernel(
    const float* __restrict__ pos, const float* __restrict__ mu,
    const float* __restrict__ sigma, const float* __restrict__ w,
    const float* __restrict__ b0)
{
    const int NT = Nn / 32;
    int p = blockIdx.x;
    float fp = (float)p;
    int twoN1 = 2 * NT + 1;
    int bi = (int)((twoN1 - sqrtf((float)twoN1 * twoN1 - 8.0f * fp)) * 0.5f);
    if (bi < 0) bi = 0;
    if (bi > NT - 1) bi = NT - 1;
    while (bi + 1 <= NT - 1 && (bi + 1) * NT - (bi + 1) * bi / 2 <= p) bi++;
    while (bi * NT - bi * (bi - 1) / 2 > p) bi--;
    int bj = bi + (p - (bi * NT - bi * (bi - 1) / 2));

    __shared__ float st[32][33];
    int tid = threadIdx.x;
    int r  = tid >> 3;
    int c0 = (tid & 7) << 2;

    int i = bi * 32 + r;
    float pix = pos[i * 3 + 0], piy = pos[i * 3 + 1], piz = pos[i * 3 + 2];
    float val[4];
#pragma unroll
    for (int k = 0; k < 4; k++) {
        int j = bj * 32 + c0 + k;
        float dx = pix - pos[j * 3 + 0];
        float dy = piy - pos[j * 3 + 1];
        float dz = piz - pos[j * 3 + 2];
        float d = sqrtf(dx * dx + dy * dy + dz * dz + 1e-12f);
        float acc = b0[0];
#pragma unroll
        for (int t = 0; t < HSd; t++) {
            float u = (d - mu[t]) / sigma[t];
            acc = fmaf(__expf(-0.5f * u * u), w[t], acc);
        }
        val[k] = acc * LOG2E;
        st[r][c0 + k] = val[k];
    }
    float4 o4 = make_float4(val[0], val[1], val[2], val[3]);
    *reinterpret_cast<float4*>(&g_bias[(long long)i * Nn + bj * 32 + c0]) = o4;
    __syncthreads();
    if (bi != bj) {
        float4 t4;
        t4.x = st[c0 + 0][r];
        t4.y = st[c0 + 1][r];
        t4.z = st[c0 + 2][r];
        t4.w = st[c0 + 3][r];
        *reinterpret_cast<float4*>(&g_bias[(long long)(bj * 32 + r) * Nn + bi * 32 + c0]) = t4;
    }
}

// LayerNorm; output pre-rounded to tf32 (it is consumed only as GEMM A input)
__global__ void ln_kernel(const float* __restrict__ x, float* __restrict__ y,
                          const float* __restrict__ g, const float* __restrict__ b) {
    int n = blockIdx.x, t = threadIdx.x;
    float v = x[n * Dd + t];
    float s = v, sq = v * v;
#pragma unroll
    for (int o = 16; o > 0; o >>= 1) {
        s  += __shfl_xor_sync(0xffffffffu, s,  o);
        sq += __shfl_xor_sync(0xffffffffu, sq, o);
    }
    __shared__ float ss[4], ssq[4];
    if ((t & 31) == 0) { ss[t >> 5] = s; ssq[t >> 5] = sq; }
    __syncthreads();
    float S = ss[0] + ss[1] + ss[2] + ss[3];
    float Q = ssq[0] + ssq[1] + ssq[2] + ssq[3];
    float mean = S * (1.0f / Dd);
    float var  = Q * (1.0f / Dd) - mean * mean;
    y[n * Dd + t] = roundtf((v - mean) * rsqrtf(var + 1e-5f) * g[t] + b[t]);
}

// ---------------- fused flash attention (tf32 mma, cp.async pipelined) ----------------
__global__ void __launch_bounds__(256, 1)
flash_kernel(const float* __restrict__ Qg, const float* __restrict__ Kg,
             const float* __restrict__ Vg, const float* __restrict__ Bias,
             float* __restrict__ Og, float scale2)
{
    extern __shared__ uint32_t sh[];
    uint32_t* Qs = sh;                       // 128*132
    uint32_t* Ps = sh + 128 * 132;           // 128*132 (K, later P)
    uint32_t* Vs = sh + 2 * 128 * 132;       // 128*136
    float* redM = (float*)(sh + 2 * 128 * 132 + 128 * 136);   // [128][4]
    float* redS = redM + 512;                                  // [128][4]

    const int tid  = threadIdx.x;
    const int wid  = tid >> 5, lane = tid & 31;
    const int gid  = lane >> 2, tid4 = lane & 3;
    const int warpM = wid & 1, warpN = wid >> 1;
    const int qBase = blockIdx.x * 128;
    const int head  = blockIdx.y;
    const int r0 = warpM * 64;
    const int c0 = warpN * 32;

    const float* Qh = Qg + (long long)head * Nn * Dd;
    const float* Kh = Kg + (long long)head * Nn * Dd;
    const float* Vh = Vg + (long long)head * Nn * Dd;

    const uint32_t qsb = (uint32_t)__cvta_generic_to_shared(Qs);
    const uint32_t psb = (uint32_t)__cvta_generic_to_shared(Ps);
    const uint32_t vsb = (uint32_t)__cvta_generic_to_shared(Vs);

#pragma unroll
    for (int it = 0; it < 16; it++) {
        int idx = (tid + it * 256) * 4;
        int r = idx >> 7, kk = idx & 127;
        cpasync16(qsb + (r * 132 + kk) * 4, &Qh[(long long)(qBase + r) * Dd + kk]);
    }
    CP_COMMIT();

    float accO[4][4][4];
#pragma unroll
    for (int mi = 0; mi < 4; mi++)
#pragma unroll
        for (int ni = 0; ni < 4; ni++)
#pragma unroll
            for (int r = 0; r < 4; r++) accO[mi][ni][r] = 0.f;
    float mrow[4][2], lrow[4][2];
#pragma unroll
    for (int mi = 0; mi < 4; mi++) {
        mrow[mi][0] = -1e30f; mrow[mi][1] = -1e30f;
        lrow[mi][0] = 0.f;    lrow[mi][1] = 0.f;
    }

    for (int j = 0; j < 16; j++) {
        const int kBase = j * 128;
#pragma unroll
        for (int it = 0; it < 16; it++) {
            int idx = (tid + it * 256) * 4;
            int c = idx >> 7, kk = idx & 127;
            cpasync16(psb + (c * 132 + kk) * 4, &Kh[(long long)(kBase + c) * Dd + kk]);
        }
        CP_COMMIT();
#pragma unroll
        for (int it = 0; it < 16; it++) {
            int idx = (tid + it * 256) * 4;
            int kr = idx >> 7, c = idx & 127;
            cpasync16(vsb + (kr * 136 + c) * 4, &Vh[(long long)(kBase + kr) * Dd + c]);
        }
        CP_COMMIT();
        CP_WAIT1();
        __syncthreads();

        float2 bl[4][2][4];
#pragma unroll
        for (int mi = 0; mi < 4; mi++)
#pragma unroll
            for (int half = 0; half < 2; half++) {
                int rl = r0 + mi * 16 + gid + half * 8;
                long long brow = (long long)(qBase + rl) * Nn + kBase;
#pragma unroll
                for (int ni = 0; ni < 4; ni++)
                    bl[mi][half][ni] = *reinterpret_cast<const float2*>(
                        &Bias[brow + c0 + ni * 8 + tid4 * 2]);
            }

        float accS[4][4][4];
#pragma unroll
        for (int mi = 0; mi < 4; mi++)
#pragma unroll
            for (int ni = 0; ni < 4; ni++)
#pragma unroll
                for (int r = 0; r < 4; r++) accS[mi][ni][r] = 0.f;
#pragma unroll
        for (int ks = 0; ks < 16; ks++) {
            const int kk = ks * 8;
            uint32_t a[4][4], b[4][2];
#pragma unroll
            for (int mi = 0; mi < 4; mi++) {
                int r = r0 + mi * 16 + gid;
                a[mi][0] = Qs[r * 132 + kk + tid4];
                a[mi][1] = Qs[(r + 8) * 132 + kk + tid4];
                a[mi][2] = Qs[r * 132 + kk + tid4 + 4];
                a[mi][3] = Qs[(r + 8) * 132 + kk + tid4 + 4];
            }
#pragma unroll
            for (int ni = 0; ni < 4; ni++) {
                int col = c0 + ni * 8 + gid;
                b[ni][0] = Ps[col * 132 + kk + tid4];
                b[ni][1] = Ps[col * 132 + kk + tid4 + 4];
            }
#pragma unroll
            for (int mi = 0; mi < 4; mi++)
#pragma unroll
                for (int ni = 0; ni < 4; ni++) {
                    asm volatile(
                        "mma.sync.aligned.m16n8k8.row.col.f32.tf32.tf32.f32 "
                        "{%0,%1,%2,%3}, {%4,%5,%6,%7}, {%8,%9}, {%0,%1,%2,%3};"
                        : "+f"(accS[mi][ni][0]), "+f"(accS[mi][ni][1]),
                          "+f"(accS[mi][ni][2]), "+f"(accS[mi][ni][3])
                        : "r"(a[mi][0]), "r"(a[mi][1]), "r"(a[mi][2]), "r"(a[mi][3]),
                          "r"(b[ni][0]), "r"(b[ni][1]));
                }
        }
        __syncthreads();

#pragma unroll
        for (int mi = 0; mi < 4; mi++) {
#pragma unroll
            for (int half = 0; half < 2; half++) {
                int rl = r0 + mi * 16 + gid + half * 8;
                float rmax = -1e30f;
#pragma unroll
                for (int ni = 0; ni < 4; ni++) {
                    float2 bb = bl[mi][half][ni];
                    float s0 = fmaf(accS[mi][ni][half * 2 + 0], scale2, bb.x);
                    float s1 = fmaf(accS[mi][ni][half * 2 + 1], scale2, bb.y);
                    accS[mi][ni][half * 2 + 0] = s0;
                    accS[mi][ni][half * 2 + 1] = s1;
                    rmax = fmaxf(rmax, fmaxf(s0, s1));
                }
                rmax = fmaxf(rmax, __shfl_xor_sync(0xffffffffu, rmax, 1));
                rmax = fmaxf(rmax, __shfl_xor_sync(0xffffffffu, rmax, 2));
                if (tid4 == 0) redM[rl * 4 + warpN] = rmax;
            }
        }
        __syncthreads();

#pragma unroll
        for (int mi = 0; mi < 4; mi++) {
#pragma unroll
            for (int half = 0; half < 2; half++) {
                int rl = r0 + mi * 16 + gid + half * 8;
                float tm = fmaxf(fmaxf(redM[rl * 4 + 0], redM[rl * 4 + 1]),
                                 fmaxf(redM[rl * 4 + 2], redM[rl * 4 + 3]));
                float mold = mrow[mi][half];
                float mnew = fmaxf(mold, tm);
                float fac  = exp2f(mold - mnew);
                mrow[mi][half] = mnew;
                lrow[mi][half] *= fac;
                float psum = 0.f;
#pragma unroll
                for (int ni = 0; ni < 4; ni++) {
                    float p0 = exp2f(accS[mi][ni][half * 2 + 0] - mnew);
                    float p1 = exp2f(accS[mi][ni][half * 2 + 1] - mnew);
                    accS[mi][ni][half * 2 + 0] = p0;
                    accS[mi][ni][half * 2 + 1] = p1;
                    psum += p0 + p1;
                    accO[mi][ni][half * 2 + 0] *= fac;
                    accO[mi][ni][half * 2 + 1] *= fac;
                }
                psum += __shfl_xor_sync(0xffffffffu, psum, 1);
                psum += __shfl_xor_sync(0xffffffffu, psum, 2);
                if (tid4 == 0) redS[rl * 4 + warpN] = psum;
            }
        }
#pragma unroll
        for (int mi = 0; mi < 4; mi++)
#pragma unroll
            for (int half = 0; half < 2; half++) {
                int rl = r0 + mi * 16 + gid + half * 8;
#pragma unroll
                for (int ni = 0; ni < 4; ni++) {
                    int cl = c0 + ni * 8 + tid4 * 2;
                    Ps[rl * 132 + cl]     = f2tf32(accS[mi][ni][half * 2 + 0]);
                    Ps[rl * 132 + cl + 1] = f2tf32(accS[mi][ni][half * 2 + 1]);
                }
            }
        CP_WAIT0();
        __syncthreads();

#pragma unroll
        for (int mi = 0; mi < 4; mi++)
#pragma unroll
            for (int half = 0; half < 2; half++) {
                int rl = r0 + mi * 16 + gid + half * 8;
                lrow[mi][half] += redS[rl * 4 + 0] + redS[rl * 4 + 1]
                                + redS[rl * 4 + 2] + redS[rl * 4 + 3];
            }

#pragma unroll
        for (int ks = 0; ks < 16; ks++) {
            const int kk = ks * 8;
            uint32_t a[4][4], b[4][2];
#pragma unroll
            for (int mi = 0; mi < 4; mi++) {
                int r = r0 + mi * 16 + gid;
                a[mi][0] = Ps[r * 132 + kk + tid4];
                a[mi][1] = Ps[(r + 8) * 132 + kk + tid4];
                a[mi][2] = Ps[r * 132 + kk + tid4 + 4];
                a[mi][3] = Ps[(r + 8) * 132 + kk + tid4 + 4];
            }
#pragma unroll
            for (int ni = 0; ni < 4; ni++) {
                int col = c0 + ni * 8 + gid;
                b[ni][0] = Vs[(kk + tid4) * 136 + col];
                b[ni][1] = Vs[(kk + tid4 + 4) * 136 + col];
            }
#pragma unroll
            for (int mi = 0; mi < 4; mi++)
#pragma unroll
                for (int ni = 0; ni < 4; ni++) {
                    asm volatile(
                        "mma.sync.aligned.m16n8k8.row.col.f32.tf32.tf32.f32 "
                        "{%0,%1,%2,%3}, {%4,%5,%6,%7}, {%8,%9}, {%0,%1,%2,%3};"
                        : "+f"(accO[mi][ni][0]), "+f"(accO[mi][ni][1]),
                          "+f"(accO[mi][ni][2]), "+f"(accO[mi][ni][3])
                        : "r"(a[mi][0]), "r"(a[mi][1]), "r"(a[mi][2]), "r"(a[mi][3]),
                          "r"(b[ni][0]), "r"(b[ni][1]));
                }
        }
        __syncthreads();
    }

    // epilogue: O / l, pre-rounded (consumed as A of Wo gemm)
#pragma unroll
    for (int mi = 0; mi < 4; mi++)
#pragma unroll
        for (int half = 0; half < 2; half++) {
            int rl = r0 + mi * 16 + gid + half * 8;
            float inv = 1.0f / lrow[mi][half];
#pragma unroll
            for (int ni = 0; ni < 4; ni++) {
                int cl = c0 + ni * 8 + tid4 * 2;
                float2 ov;
                ov.x = roundtf(accO[mi][ni][half * 2 + 0] * inv);
                ov.y = roundtf(accO[mi][ni][half * 2 + 1] * inv);
                *reinterpret_cast<float2*>(
                    &Og[(long long)(qBase + rl) * (Hh * Dd) + head * Dd + cl]) = ov;
            }
        }
}

// ---------------- pre-converted tf32 GEMM: cp.async double-buffered (dynamic smem) ----
// A and B must already hold tf32-rounded floats.
// EPI: 0=+bias  1=round(gelu(+bias))  2=C+=acc+bias  5=round(+bias)
template <int BM, int BN, int EPI>
struct GemmPcSmem {
    static constexpr int BK   = 32;
    static constexpr int LDAr = BK + 4;
    static constexpr int LDBr = BN + 8;
    static constexpr int AU   = 2 * BM * LDAr;          // u32 count (2 buffers)
    static constexpr int BU   = 2 * BK * LDBr;
    static constexpr int BYTES = (AU + BU) * 4;
};

template <int BM, int BN, int EPI>
__global__ void __launch_bounds__(256)
gemm_pc(const float* __restrict__ A, int lda, long long sA,
        const float* __restrict__ B, int ldb, long long sB,
        float* __restrict__ C, int ldc, long long sC,
        const float* __restrict__ bias, int sBias,
        int M, int Nc, int K)
{
    constexpr int BK   = 32;
    constexpr int LDAr = BK + 4;     // 36
    constexpr int LDBr = BN + 8;
    constexpr int MI   = BM / 32;
    constexpr int NI   = BN / 32;

    const int z = blockIdx.z;
    A += (long long)z * sA;
    B += (long long)z * sB;
    C += (long long)z * sC;
    bias += (long long)z * sBias;

    extern __shared__ uint32_t dyn[];
    uint32_t* As = dyn;                                 // 2 * BM * LDAr
    uint32_t* Bs = dyn + 2 * BM * LDAr;                 // 2 * BK * LDBr

    const int tid  = threadIdx.x;
    const int wid  = tid >> 5;
    const int lane = tid & 31;
    const int gid  = lane >> 2;
    const int tid4 = lane & 3;
    const int warpM = wid & 1;
    const int warpN = wid >> 1;
    const int rowBase = blockIdx.y * BM;
    const int colBase = blockIdx.x * BN;

    const uint32_t asb = (uint32_t)__cvta_generic_to_shared(As);
    const uint32_t bsb = (uint32_t)__cvta_generic_to_shared(Bs);

    auto stage = [&](int kt, int buf) {
        const int k0 = kt * BK;
        const uint32_t ab = asb + buf * (BM * LDAr * 4);
        const uint32_t bb = bsb + buf * (BK * LDBr * 4);
#pragma unroll
        for (int it = 0; it < (BM * BK) / 1024; it++) {
            int idx = (tid + it * 256) * 4;
            int r  = idx / BK;
            int kk = idx % BK;
            cpasync16(ab + (r * LDAr + kk) * 4, &A[(long long)(rowBase + r) * lda + k0 + kk]);
        }
#pragma unroll
        for (int it = 0; it < (BN * BK) / 1024; it++) {
            int idx = (tid + it * 256) * 4;
            int c  = idx % BN;
            int kr = idx / BN;
            cpasync16(bb + (kr * LDBr + c) * 4, &B[(long long)(k0 + kr) * ldb + colBase + c]);
        }
        CP_COMMIT();
    };

    float acc[MI][NI][4];
#pragma unroll
    for (int mi = 0; mi < MI; mi++)
#pragma unroll
        for (int ni = 0; ni < NI; ni++)
#pragma unroll
            for (int r = 0; r < 4; r++) acc[mi][ni][r] = 0.f;

    const int nk = K / BK;
    stage(0, 0);

    for (int kt = 0; kt < nk; kt++) {
        if (kt + 1 < nk) { stage(kt + 1, (kt + 1) & 1); CP_WAIT1(); }
        else             { CP_WAIT0(); }
        __syncthreads();

        const uint32_t* Ab = As + (kt & 1) * (BM * LDAr);
        const uint32_t* Bb = Bs + (kt & 1) * (BK * LDBr);
#pragma unroll
        for (int ks = 0; ks < 4; ks++) {
            const int kk = ks * 8;
            uint32_t a[MI][4], b[NI][2];
#pragma unroll
            for (int mi = 0; mi < MI; mi++) {
                int r = warpM * (BM / 2) + mi * 16 + gid;
                a[mi][0] = Ab[r * LDAr + kk + tid4];
                a[mi][1] = Ab[(r + 8) * LDAr + kk + tid4];
                a[mi][2] = Ab[r * LDAr + kk + tid4 + 4];
                a[mi][3] = Ab[(r + 8) * LDAr + kk + tid4 + 4];
            }
#pragma unroll
            for (int ni = 0; ni < NI; ni++) {
                int col = warpN * (BN / 4) + ni * 8 + gid;
                b[ni][0] = Bb[(kk + tid4) * LDBr + col];
                b[ni][1] = Bb[(kk + tid4 + 4) * LDBr + col];
            }
#pragma unroll
            for (int mi = 0; mi < MI; mi++)
#pragma unroll
                for (int ni = 0; ni < NI; ni++) {
                    asm volatile(
                        "mma.sync.aligned.m16n8k8.row.col.f32.tf32.tf32.f32 "
                        "{%0,%1,%2,%3}, {%4,%5,%6,%7}, {%8,%9}, {%0,%1,%2,%3};"
                        : "+f"(acc[mi][ni][0]), "+f"(acc[mi][ni][1]),
                          "+f"(acc[mi][ni][2]), "+f"(acc[mi][ni][3])
                        : "r"(a[mi][0]), "r"(a[mi][1]), "r"(a[mi][2]), "r"(a[mi][3]),
                          "r"(b[ni][0]), "r"(b[ni][1]));
                }
        }
        __syncthreads();
    }

#pragma unroll
    for (int mi = 0; mi < MI; mi++) {
#pragma unroll
        for (int ni = 0; ni < NI; ni++) {
#pragma unroll
            for (int half = 0; half < 2; half++) {
                int row = rowBase + warpM * (BM / 2) + mi * 16 + gid + half * 8;
                int col = colBase + warpN * (BN / 4) + ni * 8 + tid4 * 2;
                float v0 = acc[mi][ni][half * 2 + 0];
                float v1 = acc[mi][ni][half * 2 + 1];
                long long ci = (long long)row * ldc + col;
                if (EPI == 0) {
                    C[ci]     = v0 + bias[col];
                    C[ci + 1] = v1 + bias[col + 1];
                } else if (EPI == 1) {
                    v0 += bias[col];
                    v1 += bias[col + 1];
                    C[ci]     = roundtf(0.5f * v0 * (1.0f + erff(v0 * 0.70710678118654752f)));
                    C[ci + 1] = roundtf(0.5f * v1 * (1.0f + erff(v1 * 0.70710678118654752f)));
                } else if (EPI == 2) {
                    C[ci]     += v0 + bias[col];
                    C[ci + 1] += v1 + bias[col + 1];
                } else if (EPI == 5) {
                    C[ci]     = roundtf(v0 + bias[col]);
                    C[ci + 1] = roundtf(v1 + bias[col + 1]);
                } else {
                    C[ci]     = v0;
                    C[ci + 1] = v1;
                }
            }
        }
    }
}

// ---------------- conversion-staging tf32 GEMM (only for final out gemm) ----------------
template <int BM, int BN>
__global__ void __launch_bounds__(256, 2)
gemm_tf32(const float* __restrict__ A, int lda,
          const float* __restrict__ B, int ldb,
          float* __restrict__ C, int ldc,
          const float* __restrict__ bias,
          int M, int Nc, int K)
{
    constexpr int BK   = 32;
    constexpr int LDAr = BK + 4;
    constexpr int LDBr = BN + 8;
    constexpr int MI   = BM / 32;
    constexpr int NI   = BN / 32;

    __shared__ uint32_t As[BM * LDAr];
    __shared__ uint32_t Bs[BK * LDBr];

    const int tid  = threadIdx.x;
    const int wid  = tid >> 5;
    const int lane = tid & 31;
    const int gid  = lane >> 2;
    const int tid4 = lane & 3;
    const int warpM = wid & 1;
    const int warpN = wid >> 1;
    const int rowBase = blockIdx.y * BM;
    const int colBase = blockIdx.x * BN;

    float acc[MI][NI][4];
#pragma unroll
    for (int mi = 0; mi < MI; mi++)
#pragma unroll
        for (int ni = 0; ni < NI; ni++)
#pragma unroll
            for (int r = 0; r < 4; r++) acc[mi][ni][r] = 0.f;

    for (int k0 = 0; k0 < K; k0 += BK) {
#pragma unroll
        for (int it = 0; it < (BM * BK) / 1024; it++) {
            int idx = (tid + it * 256) * 4;
            int r  = idx / BK;
            int kk = idx % BK;
            float4 av = *reinterpret_cast<const float4*>(
                &A[(long long)(rowBase + r) * lda + k0 + kk]);
            uint4 o4; o4.x = f2tf32(av.x); o4.y = f2tf32(av.y);
            o4.z = f2tf32(av.z); o4.w = f2tf32(av.w);
            *reinterpret_cast<uint4*>(&As[r * LDAr + kk]) = o4;
        }
#pragma unroll
        for (int it = 0; it < (BN * BK) / 1024; it++) {
            int idx = (tid + it * 256) * 4;
            int c  = idx % BN;
            int kr = idx / BN;
            float4 bv = *reinterpret_cast<const float4*>(
                &B[(long long)(k0 + kr) * ldb + colBase + c]);
            uint4 o4; o4.x = f2tf32(bv.x); o4.y = f2tf32(bv.y);
            o4.z = f2tf32(bv.z); o4.w = f2tf32(bv.w);
            *reinterpret_cast<uint4*>(&Bs[kr * LDBr + c]) = o4;
        }
        __syncthreads();

#pragma unroll
        for (int ks = 0; ks < 4; ks++) {
            const int kk = ks * 8;
            uint32_t a[MI][4], b[NI][2];
#pragma unroll
            for (int mi = 0; mi < MI; mi++) {
                int r = warpM * (BM / 2) + mi * 16 + gid;
                a[mi][0] = As[r * LDAr + kk + tid4];
                a[mi][1] = As[(r + 8) * LDAr + kk + tid4];
                a[mi][2] = As[r * LDAr + kk + tid4 + 4];
                a[mi][3] = As[(r + 8) * LDAr + kk + tid4 + 4];
            }
#pragma unroll
            for (int ni = 0; ni < NI; ni++) {
                int col = warpN * (BN / 4) + ni * 8 + gid;
                b[ni][0] = Bs[(kk + tid4) * LDBr + col];
                b[ni][1] = Bs[(kk + tid4 + 4) * LDBr + col];
            }
#pragma unroll
            for (int mi = 0; mi < MI; mi++)
#pragma unroll
                for (int ni = 0; ni < NI; ni++) {
                    asm volatile(
                        "mma.sync.aligned.m16n8k8.row.col.f32.tf32.tf32.f32 "
                        "{%0,%1,%2,%3}, {%4,%5,%6,%7}, {%8,%9}, {%0,%1,%2,%3};"
                        : "+f"(acc[mi][ni][0]), "+f"(acc[mi][ni][1]),
                          "+f"(acc[mi][ni][2]), "+f"(acc[mi][ni][3])
                        : "r"(a[mi][0]), "r"(a[mi][1]), "r"(a[mi][2]), "r"(a[mi][3]),
                          "r"(b[ni][0]), "r"(b[ni][1]));
                }
        }
        __syncthreads();
    }

#pragma unroll
    for (int mi = 0; mi < MI; mi++) {
#pragma unroll
        for (int ni = 0; ni < NI; ni++) {
#pragma unroll
            for (int half = 0; half < 2; half++) {
                int row = rowBase + warpM * (BM / 2) + mi * 16 + gid + half * 8;
                int col = colBase + warpN * (BN / 4) + ni * 8 + tid4 * 2;
                long long ci = (long long)row * ldc + col;
                C[ci]     = acc[mi][ni][half * 2 + 0] + bias[col];
                C[ci + 1] = acc[mi][ni][half * 2 + 1] + bias[col + 1];
            }
        }
    }
}

// ---------------- launcher ----------------
extern "C" void kernel_launch(void* const* d_in, const int* in_sizes, int n_in,
                              void* d_out, int out_size)
{
    (void)n_in; (void)out_size;
    const float* x         = (const float*)d_in[0];
    const int*   ei        = (const int*)  d_in[1];
    const float* pos       = (const float*)d_in[3];
    const float* node_in_w = (const float*)d_in[4];
    const float* node_in_b = (const float*)d_in[5];
    const float* z_in      = (const float*)d_in[8];
    const float* z_out     = (const float*)d_in[9];
    const float* sp_mu     = (const float*)d_in[10];
    const float* sp_sigma  = (const float*)d_in[11];
    const float* sp_w      = (const float*)d_in[12];
    const float* sp_b      = (const float*)d_in[13];
    const float* Wq        = (const float*)d_in[14];
    const float* bq        = (const float*)d_in[15];
    const float* Wk        = (const float*)d_in[16];
    const float* bk        = (const float*)d_in[17];
    const float* Wv        = (const float*)d_in[18];
    const float* bv        = (const float*)d_in[19];
    const float* Wo        = (const float*)d_in[20];
    const float* bo        = (const float*)d_in[21];
    const float* ln1_g     = (const float*)d_in[22];
    const float* ln1_b     = (const float*)d_in[23];
    const float* ln2_g     = (const float*)d_in[24];
    const float* ln2_b     = (const float*)d_in[25];
    const float* ff1_w     = (const float*)d_in[26];
    const float* ff1_b     = (const float*)d_in[27];
    const float* ff2_w     = (const float*)d_in[28];
    const float* ff2_b     = (const float*)d_in[29];
    const float* out_w     = (const float*)d_in[30];
    const float* out_b     = (const float*)d_in[31];
    float* out = (float*)d_out;

    const int E = in_sizes[1] / 2;
    const float scale2 = 0.08838834764831845f * LOG2E;

    float *p_h, *p_xn, *p_bias, *p_qkv, *p_o, *p_ff;
    float *p_wqkv, *p_bqkv, *p_wo, *p_wff1, *p_wff2;
    cudaGetSymbolAddress((void**)&p_h,    g_h);
    cudaGetSymbolAddress((void**)&p_xn,   g_xn);
    cudaGetSymbolAddress((void**)&p_bias, g_bias);
    cudaGetSymbolAddress((void**)&p_qkv,  g_qkv);
    cudaGetSymbolAddress((void**)&p_o,    g_o);
    cudaGetSymbolAddress((void**)&p_ff,   g_ff);
    cudaGetSymbolAddress((void**)&p_wqkv, g_wqkv);
    cudaGetSymbolAddress((void**)&p_bqkv, g_bqkv);
    cudaGetSymbolAddress((void**)&p_wo,   g_wo);
    cudaGetSymbolAddress((void**)&p_wff1, g_wff1);
    cudaGetSymbolAddress((void**)&p_wff2, g_wff2);

    const int FLASH_SMEM = (2 * 128 * 132 + 128 * 136 + 1024) * 4;
    cudaFuncSetAttribute(flash_kernel, cudaFuncAttributeMaxDynamicSharedMemorySize, FLASH_SMEM);

    // dynamic smem sizes for gemm_pc instantiations
    constexpr int SM_QKV = GemmPcSmem<128, 128, 5>::BYTES;   // 71680
    constexpr int SM_FF1 = GemmPcSmem<64, 128, 1>::BYTES;    // 53248
    constexpr int SM_SKN = GemmPcSmem<32, 64, 2>::BYTES;     // 27648
    cudaFuncSetAttribute((const void*)gemm_pc<128, 128, 5>,
                         cudaFuncAttributeMaxDynamicSharedMemorySize, SM_QKV);
    cudaFuncSetAttribute((const void*)gemm_pc<64, 128, 1>,
                         cudaFuncAttributeMaxDynamicSharedMemorySize, SM_FF1);
    cudaFuncSetAttribute((const void*)gemm_pc<32, 64, 2>,
                         cudaFuncAttributeMaxDynamicSharedMemorySize, SM_SKN);

    // weight prep (rounded once)
    prep_qkv_w<<<(Ll * 3 * Hh * Dd * Dd + 255) / 256, 256>>>(Wq, Wk, Wv);
    prep_qkv_b<<<(Ll * 3 * Hh * Dd + 255) / 256, 256>>>(bq, bk, bv);
    prep_round<<<(Ll * Hh * Dd * Dd + 255) / 256, 256>>>(Wo, p_wo, Ll * Hh * Dd * Dd);
    prep_round<<<(Ll * Dd * FFd + 255) / 256, 256>>>(ff1_w, p_wff1, Ll * Dd * FFd);
    prep_round<<<(Ll * FFd * Dd + 255) / 256, 256>>>(ff2_w, p_wff2, Ll * FFd * Dd);

    deg_zero_kernel<<<(Nn + 255) / 256, 256>>>();
    deg_count_kernel<<<(E + 255) / 256, 256>>>(ei, E);
    embed_kernel<<<Nn, Dd>>>(x, node_in_w, node_in_b, z_in, z_out);
    {
        const int NT = Nn / 32;
        spbias_tri_kernel<<<NT * (NT + 1) / 2, 256>>>(pos, sp_mu, sp_sigma, sp_w, sp_b);
    }

    const long long sHead = (long long)Nn * Dd;
    const long long sW    = (long long)Dd * Dd;

    for (int l = 0; l < Ll; l++) {
        ln_kernel<<<Nn, Dd>>>(p_h, p_xn, ln1_g + l * Dd, ln1_b + l * Dd);

        // fused QKV: one launch, z = 3*8 = 24 batches, 384 blocks
        gemm_pc<128, 128, 5><<<dim3(1, 16, 24), 256, SM_QKV>>>(
            p_xn, Dd, 0,
            p_wqkv + (long long)l * 3 * Hh * sW, Dd, sW,
            p_qkv, Dd, sHead,
            p_bqkv + (long long)l * 3 * Hh * Dd, Dd,
            Nn, Dd, Dd);

        // fused attention
        flash_kernel<<<dim3(Nn / 128, Hh), 256, FLASH_SMEM>>>(
            p_qkv, p_qkv + (long long)Hh * sHead, p_qkv + (long long)2 * Hh * sHead,
            p_bias, p_o, scale2);

        // h += o @ Wo + bo   (BM=32 -> 128 blocks)
        gemm_pc<32, 64, 2><<<dim3(Dd / 64, Nn / 32), 256, SM_SKN>>>(
            p_o, Hh * Dd, 0, p_wo + (long long)l * Hh * sW, Dd, 0,
            p_h, Dd, 0, bo + l * Dd, 0, Nn, Dd, Hh * Dd);

        ln_kernel<<<Nn, Dd>>>(p_h, p_xn, ln2_g + l * Dd, ln2_b + l * Dd);

        // ff = round(gelu(xn2 @ ff1 + b))   (BM=64 -> 128 blocks)
        gemm_pc<64, 128, 1><<<dim3(FFd / 128, Nn / 64), 256, SM_FF1>>>(
            p_xn, Dd, 0, p_wff1 + (long long)l * Dd * FFd, FFd, 0,
            p_ff, FFd, 0, ff1_b + l * FFd, 0, Nn, FFd, Dd);

        // h += ff @ ff2 + b   (BM=32 -> 128 blocks)
        gemm_pc<32, 64, 2><<<dim3(Dd / 64, Nn / 32), 256, SM_SKN>>>(
            p_ff, FFd, 0, p_wff2 + (long long)l * FFd * Dd, Dd, 0,
            p_h, Dd, 0, ff2_b + l * Dd, 0, Nn, Dd, FFd);
    }

    // out = h @ out_w + out_b (h not pre-rounded -> conversion path)
    gemm_tf32<64, 64><<<dim3(1, Nn / 64), 256>>>(
        p_h, Dd, out_w, OUTd, out, OUTd, out_b, Nn, OUTd, Dd);
}

// round 9
// speedup vs baseline: 3.5165x; 1.0111x over previous
#include <cuda_runtime.h>
#include <math.h>
#include <stdint.h>

// ---------------- problem constants ----------------
#define Nn   2048
#define Dd   128
#define Hh   8
#define FFd  512
#define OUTd 64
#define Ll   3
#define HSd  8
#define DEGMAX 64
#define LOG2E 1.4426950408889634f

// ---------------- device scratch (no allocations allowed) ----------------
__device__ float g_h[Nn * Dd];
__device__ float g_xn[Nn * Dd];
__device__ float g_bias[(size_t)Nn * Nn];
__device__ float g_qkv[3 * Hh * Nn * Dd];           // [m][h][n][d], tf32-rounded
__device__ float g_o[Nn * Hh * Dd];                  // tf32-rounded
__device__ float g_ff[Nn * FFd];                     // tf32-rounded
__device__ float g_wqkv[Ll * 3 * Hh * Dd * Dd];      // rounded weights
__device__ float g_bqkv[Ll * 3 * Hh * Dd];
__device__ float g_wo[Ll * Hh * Dd * Dd];
__device__ float g_wff1[Ll * Dd * FFd];
__device__ float g_wff2[Ll * FFd * Dd];
__device__ int   g_indeg[Nn];
__device__ int   g_outdeg[Nn];

// ---------------- helpers ----------------
__device__ __forceinline__ uint32_t f2tf32(float f) {
    uint32_t r;
    asm("cvt.rna.tf32.f32 %0, %1;" : "=r"(r) : "f"(f));
    return r;
}
__device__ __forceinline__ float roundtf(float f) { return __uint_as_float(f2tf32(f)); }

__device__ __forceinline__ void cpasync16(uint32_t dst, const void* src) {
    asm volatile("cp.async.cg.shared.global [%0], [%1], 16;" :: "r"(dst), "l"(src));
}
#define CP_COMMIT() asm volatile("cp.async.commit_group;")
#define CP_WAIT0()  asm volatile("cp.async.wait_group 0;")
#define CP_WAIT1()  asm volatile("cp.async.wait_group 1;")

// ---------------- prep kernels (round weights once) ----------------
__global__ void prep_qkv_w(const float* __restrict__ Wq, const float* __restrict__ Wk,
                           const float* __restrict__ Wv) {
    long long i = (long long)blockIdx.x * blockDim.x + threadIdx.x;
    const long long per = (long long)Hh * Dd * Dd;             // 131072
    const long long tot = (long long)Ll * 3 * per;
    if (i >= tot) return;
    int l = (int)(i / (3 * per));
    long long rem = i % (3 * per);
    int m = (int)(rem / per);
    long long off = rem % per;
    const float* src = (m == 0) ? Wq : (m == 1) ? Wk : Wv;
    g_wqkv[i] = roundtf(src[(long long)l * per + off]);
}

__global__ void prep_qkv_b(const float* __restrict__ bq, const float* __restrict__ bk,
                           const float* __restrict__ bv) {
    int i = blockIdx.x * blockDim.x + threadIdx.x;
    const int per = Hh * Dd;                                    // 1024
    const int tot = Ll * 3 * per;
    if (i >= tot) return;
    int l = i / (3 * per);
    int rem = i % (3 * per);
    int m = rem / per;
    int off = rem % per;
    const float* src = (m == 0) ? bq : (m == 1) ? bk : bv;
    g_bqkv[i] = src[l * per + off];
}

__global__ void prep_round(const float* __restrict__ src, float* __restrict__ dst, int n) {
    int i = blockIdx.x * blockDim.x + threadIdx.x;
    if (i < n) dst[i] = roundtf(src[i]);
}

// ---------------- small kernels ----------------
__global__ void deg_zero_kernel() {
    int i = blockIdx.x * blockDim.x + threadIdx.x;
    if (i < Nn) { g_indeg[i] = 0; g_outdeg[i] = 0; }
}

__global__ void deg_count_kernel(const int* __restrict__ ei, int E) {
    int e = blockIdx.x * blockDim.x + threadIdx.x;
    if (e < E) {
        atomicAdd(&g_outdeg[ei[e]], 1);
        atomicAdd(&g_indeg[ei[E + e]], 1);
    }
}

__global__ void embed_kernel(const float* __restrict__ x, const float* __restrict__ W,
                             const float* __restrict__ b, const float* __restrict__ z_in,
                             const float* __restrict__ z_out) {
    int n = blockIdx.x, d = threadIdx.x;
    float acc = b[d];
#pragma unroll
    for (int i = 0; i < 16; i++) acc = fmaf(x[n * 16 + i], W[i * Dd + d], acc);
    int di = min(g_indeg[n],  DEGMAX - 1);
    int dn = min(g_outdeg[n], DEGMAX - 1);
    g_h[n * Dd + d] = acc + z_in[di * Dd + d] + z_out[dn * Dd + d];
}

// triangular spatial bias (writes bias * LOG2E)
__global__ void __launch_bounds__(256) spbias_tri_kernel(
    const float* __restrict__ pos, const float* __restrict__ mu,
    const float* __restrict__ sigma, const float* __restrict__ w,
    const float* __restrict__ b0)
{
    const int NT = Nn / 32;
    int p = blockIdx.x;
    float fp = (float)p;
    int twoN1 = 2 * NT + 1;
    int bi = (int)((twoN1 - sqrtf((float)twoN1 * twoN1 - 8.0f * fp)) * 0.5f);
    if (bi < 0) bi = 0;
    if (bi > NT - 1) bi = NT - 1;
    while (bi + 1 <= NT - 1 && (bi + 1) * NT - (bi + 1) * bi / 2 <= p) bi++;
    while (bi * NT - bi * (bi - 1) / 2 > p) bi--;
    int bj = bi + (p - (bi * NT - bi * (bi - 1) / 2));

    __shared__ float st[32][33];
    int tid = threadIdx.x;
    int r  = tid >> 3;
    int c0 = (tid & 7) << 2;

    int i = bi * 32 + r;
    float pix = pos[i * 3 + 0], piy = pos[i * 3 + 1], piz = pos[i * 3 + 2];
    float val[4];
#pragma unroll
    for (int k = 0; k < 4; k++) {
        int j = bj * 32 + c0 + k;
        float dx = pix - pos[j * 3 + 0];
        float dy = piy - pos[j * 3 + 1];
        float dz = piz - pos[j * 3 + 2];
        float d = sqrtf(dx * dx + dy * dy + dz * dz + 1e-12f);
        float acc = b0[0];
#pragma unroll
        for (int t = 0; t < HSd; t++) {
            float u = (d - mu[t]) / sigma[t];
            acc = fmaf(__expf(-0.5f * u * u), w[t], acc);
        }
        val[k] = acc * LOG2E;
        st[r][c0 + k] = val[k];
    }
    float4 o4 = make_float4(val[0], val[1], val[2], val[3]);
    *reinterpret_cast<float4*>(&g_bias[(long long)i * Nn + bj * 32 + c0]) = o4;
    __syncthreads();
    if (bi != bj) {
        float4 t4;
        t4.x = st[c0 + 0][r];
        t4.y = st[c0 + 1][r];
        t4.z = st[c0 + 2][r];
        t4.w = st[c0 + 3][r];
        *reinterpret_cast<float4*>(&g_bias[(long long)(bj * 32 + r) * Nn + bi * 32 + c0]) = t4;
    }
}

// LayerNorm; output pre-rounded to tf32 (it is consumed only as GEMM A input)
__global__ void ln_kernel(const float* __restrict__ x, float* __restrict__ y,
                          const float* __restrict__ g, const float* __restrict__ b) {
    int n = blockIdx.x, t = threadIdx.x;
    float v = x[n * Dd + t];
    float s = v, sq = v * v;
#pragma unroll
    for (int o = 16; o > 0; o >>= 1) {
        s  += __shfl_xor_sync(0xffffffffu, s,  o);
        sq += __shfl_xor_sync(0xffffffffu, sq, o);
    }
    __shared__ float ss[4], ssq[4];
    if ((t & 31) == 0) { ss[t >> 5] = s; ssq[t >> 5] = sq; }
    __syncthreads();
    float S = ss[0] + ss[1] + ss[2] + ss[3];
    float Q = ssq[0] + ssq[1] + ssq[2] + ssq[3];
    float mean = S * (1.0f / Dd);
    float var  = Q * (1.0f / Dd) - mean * mean;
    y[n * Dd + t] = roundtf((v - mean) * rsqrtf(var + 1e-5f) * g[t] + b[t]);
}

// ---------------- fused flash attention: 8x1 warp grid, warp-local softmax ----------------
// Each warp owns 16 complete score rows (rows wid*16 + gid, +8). NI=16 covers all 128 cols.
// Softmax reductions are quad-lane shfl only. 3 block barriers per key-tile iteration.
__global__ void __launch_bounds__(256, 1)
flash_kernel(const float* __restrict__ Qg, const float* __restrict__ Kg,
             const float* __restrict__ Vg, const float* __restrict__ Bias,
             float* __restrict__ Og, float scale2)
{
    extern __shared__ uint32_t sh[];
    uint32_t* Qs = sh;                       // 128*132
    uint32_t* Ps = sh + 128 * 132;           // 128*132 (K, later P)
    uint32_t* Vs = sh + 2 * 128 * 132;       // 128*136

    const int tid  = threadIdx.x;
    const int wid  = tid >> 5, lane = tid & 31;
    const int gid  = lane >> 2, tid4 = lane & 3;
    const int qBase = blockIdx.x * 128;
    const int head  = blockIdx.y;
    const int r0 = wid * 16;                 // warp's 16 rows

    const float* Qh = Qg + (long long)head * Nn * Dd;
    const float* Kh = Kg + (long long)head * Nn * Dd;
    const float* Vh = Vg + (long long)head * Nn * Dd;

    const uint32_t qsb = (uint32_t)__cvta_generic_to_shared(Qs);
    const uint32_t psb = (uint32_t)__cvta_generic_to_shared(Ps);
    const uint32_t vsb = (uint32_t)__cvta_generic_to_shared(Vs);

    // stage Q tile (group)
#pragma unroll
    for (int it = 0; it < 16; it++) {
        int idx = (tid + it * 256) * 4;
        int r = idx >> 7, kk = idx & 127;
        cpasync16(qsb + (r * 132 + kk) * 4, &Qh[(long long)(qBase + r) * Dd + kk]);
    }
    CP_COMMIT();

    float accO[16][4];
#pragma unroll
    for (int ni = 0; ni < 16; ni++)
#pragma unroll
        for (int r = 0; r < 4; r++) accO[ni][r] = 0.f;
    float mrow[2] = {-1e30f, -1e30f};
    float lrow[2] = {0.f, 0.f};

    for (int j = 0; j < 16; j++) {
        const int kBase = j * 128;
        // stage K (own group)
#pragma unroll
        for (int it = 0; it < 16; it++) {
            int idx = (tid + it * 256) * 4;
            int c = idx >> 7, kk = idx & 127;
            cpasync16(psb + (c * 132 + kk) * 4, &Kh[(long long)(kBase + c) * Dd + kk]);
        }
        CP_COMMIT();
        // stage V (own group) — needed only at PV
#pragma unroll
        for (int it = 0; it < 16; it++) {
            int idx = (tid + it * 256) * 4;
            int kr = idx >> 7, c = idx & 127;
            cpasync16(vsb + (kr * 136 + c) * 4, &Vh[(long long)(kBase + kr) * Dd + c]);
        }
        CP_COMMIT();
        CP_WAIT1();            // Q(+prior) and K arrived; V in flight
        __syncthreads();

        // bias burst: this warp's 2 row-halves x 16 col-groups
        float2 bl[2][16];
#pragma unroll
        for (int half = 0; half < 2; half++) {
            long long brow = (long long)(qBase + r0 + gid + half * 8) * Nn + kBase;
#pragma unroll
            for (int ni = 0; ni < 16; ni++)
                bl[half][ni] = *reinterpret_cast<const float2*>(
                    &Bias[brow + ni * 8 + tid4 * 2]);
        }

        // ---- S = Q . K^T  (16 rows x 128 cols per warp) ----
        float accS[16][4];
#pragma unroll
        for (int ni = 0; ni < 16; ni++)
#pragma unroll
            for (int r = 0; r < 4; r++) accS[ni][r] = 0.f;
#pragma unroll
        for (int ks = 0; ks < 16; ks++) {
            const int kk = ks * 8;
            uint32_t a0 = Qs[(r0 + gid) * 132 + kk + tid4];
            uint32_t a1 = Qs[(r0 + gid + 8) * 132 + kk + tid4];
            uint32_t a2 = Qs[(r0 + gid) * 132 + kk + tid4 + 4];
            uint32_t a3 = Qs[(r0 + gid + 8) * 132 + kk + tid4 + 4];
#pragma unroll
            for (int ni = 0; ni < 16; ni++) {
                uint32_t b0 = Ps[(ni * 8 + gid) * 132 + kk + tid4];
                uint32_t b1 = Ps[(ni * 8 + gid) * 132 + kk + tid4 + 4];
                asm volatile(
                    "mma.sync.aligned.m16n8k8.row.col.f32.tf32.tf32.f32 "
                    "{%0,%1,%2,%3}, {%4,%5,%6,%7}, {%8,%9}, {%0,%1,%2,%3};"
                    : "+f"(accS[ni][0]), "+f"(accS[ni][1]),
                      "+f"(accS[ni][2]), "+f"(accS[ni][3])
                    : "r"(a0), "r"(a1), "r"(a2), "r"(a3), "r"(b0), "r"(b1));
            }
        }
        CP_WAIT0();            // V arrived (hidden behind S-mma)
        __syncthreads();       // all warps done reading K; V visible

        // ---- warp-local softmax (quad-lane shfl reductions) + P write ----
#pragma unroll
        for (int half = 0; half < 2; half++) {
            float rmax = -1e30f;
#pragma unroll
            for (int ni = 0; ni < 16; ni++) {
                float2 bb = bl[half][ni];
                float s0 = fmaf(accS[ni][half * 2 + 0], scale2, bb.x);
                float s1 = fmaf(accS[ni][half * 2 + 1], scale2, bb.y);
                accS[ni][half * 2 + 0] = s0;
                accS[ni][half * 2 + 1] = s1;
                rmax = fmaxf(rmax, fmaxf(s0, s1));
            }
            rmax = fmaxf(rmax, __shfl_xor_sync(0xffffffffu, rmax, 1));
            rmax = fmaxf(rmax, __shfl_xor_sync(0xffffffffu, rmax, 2));

            float mold = mrow[half];
            float mnew = fmaxf(mold, rmax);
            float fac  = exp2f(mold - mnew);
            mrow[half] = mnew;
            float psum = 0.f;
            const int rl = r0 + gid + half * 8;
#pragma unroll
            for (int ni = 0; ni < 16; ni++) {
                float p0 = exp2f(accS[ni][half * 2 + 0] - mnew);
                float p1 = exp2f(accS[ni][half * 2 + 1] - mnew);
                psum += p0 + p1;
                accO[ni][half * 2 + 0] *= fac;
                accO[ni][half * 2 + 1] *= fac;
                uint2 pw; pw.x = f2tf32(p0); pw.y = f2tf32(p1);
                *reinterpret_cast<uint2*>(&Ps[rl * 132 + ni * 8 + tid4 * 2]) = pw;
            }
            psum += __shfl_xor_sync(0xffffffffu, psum, 1);
            psum += __shfl_xor_sync(0xffffffffu, psum, 2);
            lrow[half] = lrow[half] * fac + psum;
        }

        // ---- O += P . V  (own P rows; no barrier needed after own-row write) ----
#pragma unroll
        for (int ks = 0; ks < 16; ks++) {
            const int kk = ks * 8;
            uint32_t a0 = Ps[(r0 + gid) * 132 + kk + tid4];
            uint32_t a1 = Ps[(r0 + gid + 8) * 132 + kk + tid4];
            uint32_t a2 = Ps[(r0 + gid) * 132 + kk + tid4 + 4];
            uint32_t a3 = Ps[(r0 + gid + 8) * 132 + kk + tid4 + 4];
#pragma unroll
            for (int ni = 0; ni < 16; ni++) {
                uint32_t b0 = Vs[(kk + tid4) * 136 + ni * 8 + gid];
                uint32_t b1 = Vs[(kk + tid4 + 4) * 136 + ni * 8 + gid];
                asm volatile(
                    "mma.sync.aligned.m16n8k8.row.col.f32.tf32.tf32.f32 "
                    "{%0,%1,%2,%3}, {%4,%5,%6,%7}, {%8,%9}, {%0,%1,%2,%3};"
                    : "+f"(accO[ni][0]), "+f"(accO[ni][1]),
                      "+f"(accO[ni][2]), "+f"(accO[ni][3])
                    : "r"(a0), "r"(a1), "r"(a2), "r"(a3), "r"(b0), "r"(b1));
            }
        }
        __syncthreads();       // before next iteration restages Ps/Vs
    }

    // ---- epilogue: O / l, pre-rounded ----
#pragma unroll
    for (int half = 0; half < 2; half++) {
        const int rl = r0 + gid + half * 8;
        float inv = 1.0f / lrow[half];
#pragma unroll
        for (int ni = 0; ni < 16; ni++) {
            float2 ov;
            ov.x = roundtf(accO[ni][half * 2 + 0] * inv);
            ov.y = roundtf(accO[ni][half * 2 + 1] * inv);
            *reinterpret_cast<float2*>(
                &Og[(long long)(qBase + rl) * (Hh * Dd) + head * Dd + ni * 8 + tid4 * 2]) = ov;
        }
    }
}

// ---------------- pre-converted tf32 GEMM: cp.async double-buffered (dynamic smem) ----
// A and B must already hold tf32-rounded floats.
// EPI: 0=+bias  1=round(gelu(+bias))  2=C+=acc+bias  5=round(+bias)
template <int BM, int BN, int EPI>
struct GemmPcSmem {
    static constexpr int BK   = 32;
    static constexpr int LDAr = BK + 4;
    static constexpr int LDBr = BN + 8;
    static constexpr int AU   = 2 * BM * LDAr;          // u32 count (2 buffers)
    static constexpr int BU   = 2 * BK * LDBr;
    static constexpr int BYTES = (AU + BU) * 4;
};

template <int BM, int BN, int EPI>
__global__ void __launch_bounds__(256)
gemm_pc(const float* __restrict__ A, int lda, long long sA,
        const float* __restrict__ B, int ldb, long long sB,
        float* __restrict__ C, int ldc, long long sC,
        const float* __restrict__ bias, int sBias,
        int M, int Nc, int K)
{
    constexpr int BK   = 32;
    constexpr int LDAr = BK + 4;     // 36
    constexpr int LDBr = BN + 8;
    constexpr int MI   = BM / 32;
    constexpr int NI   = BN / 32;

    const int z = blockIdx.z;
    A += (long long)z * sA;
    B += (long long)z * sB;
    C += (long long)z * sC;
    bias += (long long)z * sBias;

    extern __shared__ uint32_t dyn[];
    uint32_t* As = dyn;                                 // 2 * BM * LDAr
    uint32_t* Bs = dyn + 2 * BM * LDAr;                 // 2 * BK * LDBr

    const int tid  = threadIdx.x;
    const int wid  = tid >> 5;
    const int lane = tid & 31;
    const int gid  = lane >> 2;
    const int tid4 = lane & 3;
    const int warpM = wid & 1;
    const int warpN = wid >> 1;
    const int rowBase = blockIdx.y * BM;
    const int colBase = blockIdx.x * BN;

    const uint32_t asb = (uint32_t)__cvta_generic_to_shared(As);
    const uint32_t bsb = (uint32_t)__cvta_generic_to_shared(Bs);

    auto stage = [&](int kt, int buf) {
        const int k0 = kt * BK;
        const uint32_t ab = asb + buf * (BM * LDAr * 4);
        const uint32_t bb = bsb + buf * (BK * LDBr * 4);
#pragma unroll
        for (int it = 0; it < (BM * BK) / 1024; it++) {
            int idx = (tid + it * 256) * 4;
            int r  = idx / BK;
            int kk = idx % BK;
            cpasync16(ab + (r * LDAr + kk) * 4, &A[(long long)(rowBase + r) * lda + k0 + kk]);
        }
#pragma unroll
        for (int it = 0; it < (BN * BK) / 1024; it++) {
            int idx = (tid + it * 256) * 4;
            int c  = idx % BN;
            int kr = idx / BN;
            cpasync16(bb + (kr * LDBr + c) * 4, &B[(long long)(k0 + kr) * ldb + colBase + c]);
        }
        CP_COMMIT();
    };

    float acc[MI][NI][4];
#pragma unroll
    for (int mi = 0; mi < MI; mi++)
#pragma unroll
        for (int ni = 0; ni < NI; ni++)
#pragma unroll
            for (int r = 0; r < 4; r++) acc[mi][ni][r] = 0.f;

    const int nk = K / BK;
    stage(0, 0);

    for (int kt = 0; kt < nk; kt++) {
        if (kt + 1 < nk) { stage(kt + 1, (kt + 1) & 1); CP_WAIT1(); }
        else             { CP_WAIT0(); }
        __syncthreads();

        const uint32_t* Ab = As + (kt & 1) * (BM * LDAr);
        const uint32_t* Bb = Bs + (kt & 1) * (BK * LDBr);
#pragma unroll
        for (int ks = 0; ks < 4; ks++) {
            const int kk = ks * 8;
            uint32_t a[MI][4], b[NI][2];
#pragma unroll
            for (int mi = 0; mi < MI; mi++) {
                int r = warpM * (BM / 2) + mi * 16 + gid;
                a[mi][0] = Ab[r * LDAr + kk + tid4];
                a[mi][1] = Ab[(r + 8) * LDAr + kk + tid4];
                a[mi][2] = Ab[r * LDAr + kk + tid4 + 4];
                a[mi][3] = Ab[(r + 8) * LDAr + kk + tid4 + 4];
            }
#pragma unroll
            for (int ni = 0; ni < NI; ni++) {
                int col = warpN * (BN / 4) + ni * 8 + gid;
                b[ni][0] = Bb[(kk + tid4) * LDBr + col];
                b[ni][1] = Bb[(kk + tid4 + 4) * LDBr + col];
            }
#pragma unroll
            for (int mi = 0; mi < MI; mi++)
#pragma unroll
                for (int ni = 0; ni < NI; ni++) {
                    asm volatile(
                        "mma.sync.aligned.m16n8k8.row.col.f32.tf32.tf32.f32 "
                        "{%0,%1,%2,%3}, {%4,%5,%6,%7}, {%8,%9}, {%0,%1,%2,%3};"
                        : "+f"(acc[mi][ni][0]), "+f"(acc[mi][ni][1]),
                          "+f"(acc[mi][ni][2]), "+f"(acc[mi][ni][3])
                        : "r"(a[mi][0]), "r"(a[mi][1]), "r"(a[mi][2]), "r"(a[mi][3]),
                          "r"(b[ni][0]), "r"(b[ni][1]));
                }
        }
        __syncthreads();
    }

#pragma unroll
    for (int mi = 0; mi < MI; mi++) {
#pragma unroll
        for (int ni = 0; ni < NI; ni++) {
#pragma unroll
            for (int half = 0; half < 2; half++) {
                int row = rowBase + warpM * (BM / 2) + mi * 16 + gid + half * 8;
                int col = colBase + warpN * (BN / 4) + ni * 8 + tid4 * 2;
                float v0 = acc[mi][ni][half * 2 + 0];
                float v1 = acc[mi][ni][half * 2 + 1];
                long long ci = (long long)row * ldc + col;
                if (EPI == 0) {
                    C[ci]     = v0 + bias[col];
                    C[ci + 1] = v1 + bias[col + 1];
                } else if (EPI == 1) {
                    v0 += bias[col];
                    v1 += bias[col + 1];
                    C[ci]     = roundtf(0.5f * v0 * (1.0f + erff(v0 * 0.70710678118654752f)));
                    C[ci + 1] = roundtf(0.5f * v1 * (1.0f + erff(v1 * 0.70710678118654752f)));
                } else if (EPI == 2) {
                    C[ci]     += v0 + bias[col];
                    C[ci + 1] += v1 + bias[col + 1];
                } else if (EPI == 5) {
                    C[ci]     = roundtf(v0 + bias[col]);
                    C[ci + 1] = roundtf(v1 + bias[col + 1]);
                } else {
                    C[ci]     = v0;
                    C[ci + 1] = v1;
                }
            }
        }
    }
}

// ---------------- conversion-staging tf32 GEMM (only for final out gemm) ----------------
template <int BM, int BN>
__global__ void __launch_bounds__(256, 2)
gemm_tf32(const float* __restrict__ A, int lda,
          const float* __restrict__ B, int ldb,
          float* __restrict__ C, int ldc,
          const float* __restrict__ bias,
          int M, int Nc, int K)
{
    constexpr int BK   = 32;
    constexpr int LDAr = BK + 4;
    constexpr int LDBr = BN + 8;
    constexpr int MI   = BM / 32;
    constexpr int NI   = BN / 32;

    __shared__ uint32_t As[BM * LDAr];
    __shared__ uint32_t Bs[BK * LDBr];

    const int tid  = threadIdx.x;
    const int wid  = tid >> 5;
    const int lane = tid & 31;
    const int gid  = lane >> 2;
    const int tid4 = lane & 3;
    const int warpM = wid & 1;
    const int warpN = wid >> 1;
    const int rowBase = blockIdx.y * BM;
    const int colBase = blockIdx.x * BN;

    float acc[MI][NI][4];
#pragma unroll
    for (int mi = 0; mi < MI; mi++)
#pragma unroll
        for (int ni = 0; ni < NI; ni++)
#pragma unroll
            for (int r = 0; r < 4; r++) acc[mi][ni][r] = 0.f;

    for (int k0 = 0; k0 < K; k0 += BK) {
#pragma unroll
        for (int it = 0; it < (BM * BK) / 1024; it++) {
            int idx = (tid + it * 256) * 4;
            int r  = idx / BK;
            int kk = idx % BK;
            float4 av = *reinterpret_cast<const float4*>(
                &A[(long long)(rowBase + r) * lda + k0 + kk]);
            uint4 o4; o4.x = f2tf32(av.x); o4.y = f2tf32(av.y);
            o4.z = f2tf32(av.z); o4.w = f2tf32(av.w);
            *reinterpret_cast<uint4*>(&As[r * LDAr + kk]) = o4;
        }
#pragma unroll
        for (int it = 0; it < (BN * BK) / 1024; it++) {
            int idx = (tid + it * 256) * 4;
            int c  = idx % BN;
            int kr = idx / BN;
            float4 bv = *reinterpret_cast<const float4*>(
                &B[(long long)(k0 + kr) * ldb + colBase + c]);
            uint4 o4; o4.x = f2tf32(bv.x); o4.y = f2tf32(bv.y);
            o4.z = f2tf32(bv.z); o4.w = f2tf32(bv.w);
            *reinterpret_cast<uint4*>(&Bs[kr * LDBr + c]) = o4;
        }
        __syncthreads();

#pragma unroll
        for (int ks = 0; ks < 4; ks++) {
            const int kk = ks * 8;
            uint32_t a[MI][4], b[NI][2];
#pragma unroll
            for (int mi = 0; mi < MI; mi++) {
                int r = warpM * (BM / 2) + mi * 16 + gid;
                a[mi][0] = As[r * LDAr + kk + tid4];
                a[mi][1] = As[(r + 8) * LDAr + kk + tid4];
                a[mi][2] = As[r * LDAr + kk + tid4 + 4];
                a[mi][3] = As[(r + 8) * LDAr + kk + tid4 + 4];
            }
#pragma unroll
            for (int ni = 0; ni < NI; ni++) {
                int col = warpN * (BN / 4) + ni * 8 + gid;
                b[ni][0] = Bs[(kk + tid4) * LDBr + col];
                b[ni][1] = Bs[(kk + tid4 + 4) * LDBr + col];
            }
#pragma unroll
            for (int mi = 0; mi < MI; mi++)
#pragma unroll
                for (int ni = 0; ni < NI; ni++) {
                    asm volatile(
                        "mma.sync.aligned.m16n8k8.row.col.f32.tf32.tf32.f32 "
                        "{%0,%1,%2,%3}, {%4,%5,%6,%7}, {%8,%9}, {%0,%1,%2,%3};"
                        : "+f"(acc[mi][ni][0]), "+f"(acc[mi][ni][1]),
                          "+f"(acc[mi][ni][2]), "+f"(acc[mi][ni][3])
                        : "r"(a[mi][0]), "r"(a[mi][1]), "r"(a[mi][2]), "r"(a[mi][3]),
                          "r"(b[ni][0]), "r"(b[ni][1]));
                }
        }
        __syncthreads();
    }

#pragma unroll
    for (int mi = 0; mi < MI; mi++) {
#pragma unroll
        for (int ni = 0; ni < NI; ni++) {
#pragma unroll
            for (int half = 0; half < 2; half++) {
                int row = rowBase + warpM * (BM / 2) + mi * 16 + gid + half * 8;
                int col = colBase + warpN * (BN / 4) + ni * 8 + tid4 * 2;
                long long ci = (long long)row * ldc + col;
                C[ci]     = acc[mi][ni][half * 2 + 0] + bias[col];
                C[ci + 1] = acc[mi][ni][half * 2 + 1] + bias[col + 1];
            }
        }
    }
}

// ---------------- launcher ----------------
extern "C" void kernel_launch(void* const* d_in, const int* in_sizes, int n_in,
                              void* d_out, int out_size)
{
    (void)n_in; (void)out_size;
    const float* x         = (const float*)d_in[0];
    const int*   ei        = (const int*)  d_in[1];
    const float* pos       = (const float*)d_in[3];
    const float* node_in_w = (const float*)d_in[4];
    const float* node_in_b = (const float*)d_in[5];
    const float* z_in      = (const float*)d_in[8];
    const float* z_out     = (const float*)d_in[9];
    const float* sp_mu     = (const float*)d_in[10];
    const float* sp_sigma  = (const float*)d_in[11];
    const float* sp_w      = (const float*)d_in[12];
    const float* sp_b      = (const float*)d_in[13];
    const float* Wq        = (const float*)d_in[14];
    const float* bq        = (const float*)d_in[15];
    const float* Wk        = (const float*)d_in[16];
    const float* bk        = (const float*)d_in[17];
    const float* Wv        = (const float*)d_in[18];
    const float* bv        = (const float*)d_in[19];
    const float* Wo        = (const float*)d_in[20];
    const float* bo        = (const float*)d_in[21];
    const float* ln1_g     = (const float*)d_in[22];
    const float* ln1_b     = (const float*)d_in[23];
    const float* ln2_g     = (const float*)d_in[24];
    const float* ln2_b     = (const float*)d_in[25];
    const float* ff1_w     = (const float*)d_in[26];
    const float* ff1_b     = (const float*)d_in[27];
    const float* ff2_w     = (const float*)d_in[28];
    const float* ff2_b     = (const float*)d_in[29];
    const float* out_w     = (const float*)d_in[30];
    const float* out_b     = (const float*)d_in[31];
    float* out = (float*)d_out;

    const int E = in_sizes[1] / 2;
    const float scale2 = 0.08838834764831845f * LOG2E;

    float *p_h, *p_xn, *p_bias, *p_qkv, *p_o, *p_ff;
    float *p_wqkv, *p_bqkv, *p_wo, *p_wff1, *p_wff2;
    cudaGetSymbolAddress((void**)&p_h,    g_h);
    cudaGetSymbolAddress((void**)&p_xn,   g_xn);
    cudaGetSymbolAddress((void**)&p_bias, g_bias);
    cudaGetSymbolAddress((void**)&p_qkv,  g_qkv);
    cudaGetSymbolAddress((void**)&p_o,    g_o);
    cudaGetSymbolAddress((void**)&p_ff,   g_ff);
    cudaGetSymbolAddress((void**)&p_wqkv, g_wqkv);
    cudaGetSymbolAddress((void**)&p_bqkv, g_bqkv);
    cudaGetSymbolAddress((void**)&p_wo,   g_wo);
    cudaGetSymbolAddress((void**)&p_wff1, g_wff1);
    cudaGetSymbolAddress((void**)&p_wff2, g_wff2);

    const int FLASH_SMEM = (2 * 128 * 132 + 128 * 136) * 4;
    cudaFuncSetAttribute(flash_kernel, cudaFuncAttributeMaxDynamicSharedMemorySize, FLASH_SMEM);

    // dynamic smem sizes for gemm_pc instantiations
    constexpr int SM_QKV = GemmPcSmem<128, 128, 5>::BYTES;
    constexpr int SM_FF1 = GemmPcSmem<64, 128, 1>::BYTES;
    constexpr int SM_SKN = GemmPcSmem<32, 64, 2>::BYTES;
    cudaFuncSetAttribute((const void*)gemm_pc<128, 128, 5>,
                         cudaFuncAttributeMaxDynamicSharedMemorySize, SM_QKV);
    cudaFuncSetAttribute((const void*)gemm_pc<64, 128, 1>,
                         cudaFuncAttributeMaxDynamicSharedMemorySize, SM_FF1);
    cudaFuncSetAttribute((const void*)gemm_pc<32, 64, 2>,
                         cudaFuncAttributeMaxDynamicSharedMemorySize, SM_SKN);

    // weight prep (rounded once)
    prep_qkv_w<<<(Ll * 3 * Hh * Dd * Dd + 255) / 256, 256>>>(Wq, Wk, Wv);
    prep_qkv_b<<<(Ll * 3 * Hh * Dd + 255) / 256, 256>>>(bq, bk, bv);
    prep_round<<<(Ll * Hh * Dd * Dd + 255) / 256, 256>>>(Wo, p_wo, Ll * Hh * Dd * Dd);
    prep_round<<<(Ll * Dd * FFd + 255) / 256, 256>>>(ff1_w, p_wff1, Ll * Dd * FFd);
    prep_round<<<(Ll * FFd * Dd + 255) / 256, 256>>>(ff2_w, p_wff2, Ll * FFd * Dd);

    deg_zero_kernel<<<(Nn + 255) / 256, 256>>>();
    deg_count_kernel<<<(E + 255) / 256, 256>>>(ei, E);
    embed_kernel<<<Nn, Dd>>>(x, node_in_w, node_in_b, z_in, z_out);
    {
        const int NT = Nn / 32;
        spbias_tri_kernel<<<NT * (NT + 1) / 2, 256>>>(pos, sp_mu, sp_sigma, sp_w, sp_b);
    }

    const long long sHead = (long long)Nn * Dd;
    const long long sW    = (long long)Dd * Dd;

    for (int l = 0; l < Ll; l++) {
        ln_kernel<<<Nn, Dd>>>(p_h, p_xn, ln1_g + l * Dd, ln1_b + l * Dd);

        // fused QKV: one launch, z = 3*8 = 24 batches, 384 blocks
        gemm_pc<128, 128, 5><<<dim3(1, 16, 24), 256, SM_QKV>>>(
            p_xn, Dd, 0,
            p_wqkv + (long long)l * 3 * Hh * sW, Dd, sW,
            p_qkv, Dd, sHead,
            p_bqkv + (long long)l * 3 * Hh * Dd, Dd,
            Nn, Dd, Dd);

        // fused attention
        flash_kernel<<<dim3(Nn / 128, Hh), 256, FLASH_SMEM>>>(
            p_qkv, p_qkv + (long long)Hh * sHead, p_qkv + (long long)2 * Hh * sHead,
            p_bias, p_o, scale2);

        // h += o @ Wo + bo   (BM=32 -> 128 blocks)
        gemm_pc<32, 64, 2><<<dim3(Dd / 64, Nn / 32), 256, SM_SKN>>>(
            p_o, Hh * Dd, 0, p_wo + (long long)l * Hh * sW, Dd, 0,
            p_h, Dd, 0, bo + l * Dd, 0, Nn, Dd, Hh * Dd);

        ln_kernel<<<Nn, Dd>>>(p_h, p_xn, ln2_g + l * Dd, ln2_b + l * Dd);

        // ff = round(gelu(xn2 @ ff1 + b))   (BM=64 -> 128 blocks)
        gemm_pc<64, 128, 1><<<dim3(FFd / 128, Nn / 64), 256, SM_FF1>>>(
            p_xn, Dd, 0, p_wff1 + (long long)l * Dd * FFd, FFd, 0,
            p_ff, FFd, 0, ff1_b + l * FFd, 0, Nn, FFd, Dd);

        // h += ff @ ff2 + b   (BM=32 -> 128 blocks)
        gemm_pc<32, 64, 2><<<dim3(Dd / 64, Nn / 32), 256, SM_SKN>>>(
            p_ff, FFd, 0, p_wff2 + (long long)l * FFd * Dd, Dd, 0,
            p_h, Dd, 0, ff2_b + l * Dd, 0, Nn, Dd, FFd);
    }

    // out = h @ out_w + out_b (h not pre-rounded -> conversion path)
    gemm_tf32<64, 64><<<dim3(1, Nn / 64), 256>>>(
        p_h, Dd, out_w, OUTd, out, OUTd, out_b, Nn, OUTd, Dd);
}